// round 9
// baseline (speedup 1.0000x reference)
#include <cuda_runtime.h>
#include <cuda_bf16.h>
#include <cuda_fp16.h>
#include <cstdint>

// Problem dims
#define BB 4
#define SS 4096
#define HH 8
#define DD 64
#define HD 512
#define TOK (BB*SS)
#define ROWS (TOK*HH)          // 131072 gemm rows
#define CC 32
#define NC (SS/CC)
#define BC (BB*NC)

// ================= scratch ====================================================
__device__ float g_csum[ROWS*DD];
__device__ float g_fg  [ROWS*DD];
__device__ float g_igh [ROWS*DD];
__device__ float g_cell[ROWS*DD];
__device__ float g_chunksum[BC*HD];
__device__ float g_A [BC*HD];
__device__ float g_Bv[BC*HD];
// W pre-packed in mma B-fragment order: [ks][nt][lane][2] u32 (fp16x2 each)
__device__ uint32_t g_WhF[12288];   // GEMM1: 8 ks * 24 nt * 32 * 2
__device__ uint32_t g_WoF[4096];    // GEMM2: 8 ks * 8 nt * 32 * 2

// ================= helpers ====================================================
__device__ __forceinline__ float sigmoidf_(float v) { return 1.f / (1.f + __expf(-v)); }

__device__ __forceinline__ void split_f16(float v, unsigned short& hi, unsigned short& lo) {
    __half h = __float2half_rn(v);
    __half l = __float2half_rn(v - __half2float(h));
    hi = __half_as_ushort(h);
    lo = __half_as_ushort(l);
}

#define MMA4(c, a0,a1,a2,a3, b0,b1) \
    asm volatile("mma.sync.aligned.m16n8k16.row.col.f32.f16.f16.f32 " \
        "{%0,%1,%2,%3}, {%4,%5,%6,%7}, {%8,%9}, {%0,%1,%2,%3};" \
        : "+f"((c)[0]),"+f"((c)[1]),"+f"((c)[2]),"+f"((c)[3]) \
        : "r"(a0),"r"(a1),"r"(a2),"r"(a3),"r"(b0),"r"(b1))

// ================= prep: W -> B-fragment images (fp16, single-rounded) ========
__global__ void kprep_w(const float* __restrict__ Wh, const float* __restrict__ Wog) {
    int t = blockIdx.x * blockDim.x + threadIdx.x;
    int stride = gridDim.x * blockDim.x;
    for (int idx = t; idx < 12288; idx += stride) {
        int reg  = idx & 1;
        int lane = (idx >> 1) & 31;
        int nt   = (idx >> 6) % 24;
        int ks   = (idx >> 6) / 24;
        int nquad = nt / 6, ntl = nt % 6;
        int gate = ntl >> 1, dt = ntl & 1;
        int d = nquad*16 + dt*8 + (lane >> 2);
        int n = gate*64 + d;
        int k0 = ks*16 + (lane & 3)*2 + reg*8;
        unsigned short h0 = __half_as_ushort(__float2half_rn(Wh[(size_t)k0*192 + n]));
        unsigned short h1 = __half_as_ushort(__float2half_rn(Wh[(size_t)(k0+1)*192 + n]));
        g_WhF[idx] = (uint32_t)h0 | ((uint32_t)h1 << 16);
    }
    for (int idx = t; idx < 4096; idx += stride) {
        int reg  = idx & 1;
        int lane = (idx >> 1) & 31;
        int nt   = (idx >> 6) % 8;
        int ks   = (idx >> 6) / 8;
        int n = nt*8 + (lane >> 2);
        int k0 = ks*16 + (lane & 3)*2 + reg*8;
        unsigned short h0 = __half_as_ushort(__float2half_rn(Wog[(size_t)k0*64 + n]));
        unsigned short h1 = __half_as_ushort(__float2half_rn(Wog[(size_t)(k0+1)*64 + n]));
        g_WoF[idx] = (uint32_t)h0 | ((uint32_t)h1 << 16);
    }
}

// ================= K1: per-chunk sums of X ------------------------------------
__global__ void k1_chunksum(const float* __restrict__ x) {
    int bc = blockIdx.x;
    int b = bc / NC, c = bc % NC;
    int tid = threadIdx.x;
    const float* p = x + ((size_t)(b*SS + c*CC))*HD + tid;
    float s = 0.f;
    #pragma unroll
    for (int i = 0; i < CC; i++) s += p[(size_t)i*HD];
    g_chunksum[(size_t)bc*HD + tid] = s;
}

// ================= K3: prefix lookback + cumsum + LayerNorm ==================
__global__ __launch_bounds__(512) void k3_csum_ln(const float* __restrict__ x,
                                                  const float* __restrict__ gamma,
                                                  const float* __restrict__ beta) {
    int bc = blockIdx.x;
    int b = bc / NC, c = bc % NC;
    int tid = threadIdx.x;
    int warp = tid >> 5, lane = tid & 31;
    __shared__ float sm_s[16][33];
    __shared__ float sm_q[16][33];
    __shared__ float sm_mean[32], sm_inv[32];

    float run = 0.f;
    {
        const float* pcs = g_chunksum + (size_t)b*NC*HD + tid;
        int j = 0;
        for (; j + 4 <= c; j += 4)
            run += pcs[(size_t)(j+0)*HD] + pcs[(size_t)(j+1)*HD]
                 + pcs[(size_t)(j+2)*HD] + pcs[(size_t)(j+3)*HD];
        for (; j < c; j++) run += pcs[(size_t)j*HD];
    }

    float ga = gamma[tid], be = beta[tid];
    size_t base = ((size_t)(b*SS + c*CC))*HD + tid;
    const float* px = x + base;
    float* pc = g_csum + base;

    float r1 = run;
    #pragma unroll
    for (int i = 0; i < CC; i++) {
        float val = r1;
        r1 += px[(size_t)i*HD];
        float s = val, q = val*val;
        #pragma unroll
        for (int o = 16; o; o >>= 1) {
            s += __shfl_xor_sync(0xffffffffu, s, o);
            q += __shfl_xor_sync(0xffffffffu, q, o);
        }
        if (lane == 0) { sm_s[warp][i] = s; sm_q[warp][i] = q; }
    }
    __syncthreads();

    {
        int t = tid >> 4, k = tid & 15;
        float s = sm_s[k][t], q = sm_q[k][t];
        #pragma unroll
        for (int o = 8; o; o >>= 1) {
            s += __shfl_xor_sync(0xffffffffu, s, o);
            q += __shfl_xor_sync(0xffffffffu, q, o);
        }
        if (k == 0) {
            float m = s * (1.f/512.f);
            float v = q * (1.f/512.f) - m*m;
            sm_mean[t] = m;
            sm_inv[t]  = rsqrtf(v + 1e-5f);
        }
    }
    __syncthreads();

    float r2 = run;
    #pragma unroll
    for (int i = 0; i < CC; i++) {
        float val = r2;
        r2 += px[(size_t)i*HD];
        pc[(size_t)i*HD] = (val - sm_mean[i]) * sm_inv[i] * ga + be;
    }
}

// ================= K5: per-chunk cell-scan states =============================
__global__ void k5_chunkscan() {
    int bc = blockIdx.x;
    int b = bc / NC, c = bc % NC;
    int tid = threadIdx.x;
    size_t base = ((size_t)(b*SS + c*CC))*HD + tid;
    const float* pf = g_fg + base;
    const float* pg = g_igh + base;
    float a = 1.f, bv = 0.f;
    #pragma unroll
    for (int i = 0; i < CC; i++) {
        float f = pf[(size_t)i*HD], g = pg[(size_t)i*HD];
        a *= f;
        bv = bv * f + g;
    }
    g_A [(size_t)bc*HD + tid] = a;
    g_Bv[(size_t)bc*HD + tid] = bv;
}

// ================= K7a: lookback carry + replay cell ==========================
__global__ void k7a_cell(const float* __restrict__ initcx) {
    int bc = blockIdx.x;
    int b = bc / NC, c = bc % NC;
    int tid = threadIdx.x;

    float carry = initcx[tid];
    {
        const float* pA = g_A  + (size_t)b*NC*HD + tid;
        const float* pB = g_Bv + (size_t)b*NC*HD + tid;
        #pragma unroll 4
        for (int j = 0; j < c; j++)
            carry = pA[(size_t)j*HD] * carry + pB[(size_t)j*HD];
    }

    size_t base = ((size_t)(b*SS + c*CC))*HD + tid;
    const float* pf = g_fg + base;
    const float* pg = g_igh + base;
    float* pc = g_cell + base;
    float cell = carry;
    #pragma unroll
    for (int i = 0; i < CC; i++) {
        cell = pf[(size_t)i*HD] * cell + pg[(size_t)i*HD];
        pc[(size_t)i*HD] = cell;
    }
}

// ================= A tile converts: f32 -> fp16 hi/lo in SMEM =================
#define APITCH 136
#define A64_SMEM_BYTES (2*64*APITCH*2)    // 34816
#define A128_SMEM_BYTES (2*128*APITCH*2)  // 69632

// 64-row tile, 256 threads: r = tid>>2, k-quarter = tid&3 (32 k each).
__device__ __forceinline__ void convert_A64_256(unsigned short* Ahi, unsigned short* Alo,
                                                const float* __restrict__ x,
                                                const float* __restrict__ other,
                                                int row0, int tid) {
    int r = tid >> 2;
    int q = tid & 3;
    const float* src = (q < 2)
        ? (x     + (size_t)(row0 + r)*64 + q*32)
        : (other + (size_t)(row0 + r)*64 + (q-2)*32);
    int kbase = q*32;
    const float4* p4 = (const float4*)src;
    #pragma unroll
    for (int i = 0; i < 8; i++) {
        float4 v = p4[i];
        unsigned short h0,l0,h1,l1,h2,l2,h3,l3;
        split_f16(v.x, h0, l0);
        split_f16(v.y, h1, l1);
        split_f16(v.z, h2, l2);
        split_f16(v.w, h3, l3);
        int k = kbase + i*4;
        *(uint32_t*)&Ahi[r*APITCH + k]     = (uint32_t)h0 | ((uint32_t)h1 << 16);
        *(uint32_t*)&Ahi[r*APITCH + k + 2] = (uint32_t)h2 | ((uint32_t)h3 << 16);
        *(uint32_t*)&Alo[r*APITCH + k]     = (uint32_t)l0 | ((uint32_t)l1 << 16);
        *(uint32_t*)&Alo[r*APITCH + k + 2] = (uint32_t)l2 | ((uint32_t)l3 << 16);
    }
}

// 128-row tile, 256 threads: r = tid>>1, k-half = tid&1 (64 k each).
__device__ __forceinline__ void convert_A128_256(unsigned short* Ahi, unsigned short* Alo,
                                                 const float* __restrict__ x,
                                                 const float* __restrict__ other,
                                                 int row0, int tid) {
    int r = tid >> 1;
    int q = tid & 1;
    const float* src = (q == 0)
        ? (x     + (size_t)(row0 + r)*64)
        : (other + (size_t)(row0 + r)*64);
    int kbase = q*64;
    const float4* p4 = (const float4*)src;
    #pragma unroll
    for (int i = 0; i < 16; i++) {
        float4 v = p4[i];
        unsigned short h0,l0,h1,l1,h2,l2,h3,l3;
        split_f16(v.x, h0, l0);
        split_f16(v.y, h1, l1);
        split_f16(v.z, h2, l2);
        split_f16(v.w, h3, l3);
        int k = kbase + i*4;
        *(uint32_t*)&Ahi[r*APITCH + k]     = (uint32_t)h0 | ((uint32_t)h1 << 16);
        *(uint32_t*)&Ahi[r*APITCH + k + 2] = (uint32_t)h2 | ((uint32_t)h3 << 16);
        *(uint32_t*)&Alo[r*APITCH + k]     = (uint32_t)l0 | ((uint32_t)l1 << 16);
        *(uint32_t*)&Alo[r*APITCH + k + 2] = (uint32_t)l2 | ((uint32_t)l3 << 16);
    }
}

// ================= K4: GEMM1 via mma.sync + fused gates =======================
// Block: 256 thr (8 warps), M-tile 64. Warp = 32 rows (2 slabs) x 48 cols (nquad).
__global__ __launch_bounds__(256, 3) void k4_mma(const float* __restrict__ x,
                                                 const float* __restrict__ bhid) {
    extern __shared__ unsigned short smu[];
    unsigned short* Ahi = smu;
    unsigned short* Alo = smu + 64*APITCH;
    int tid = threadIdx.x, lane = tid & 31, wid = tid >> 5;
    int row0 = blockIdx.x * 64;

    convert_A64_256(Ahi, Alo, x, g_csum, row0, tid);
    __syncthreads();

    int sp = wid >> 2, nquad = wid & 3;      // sp: slab-pair (0..1) -> rows sp*32..+32
    int mA = sp*32 + (lane >> 2);
    int kq = (lane & 3)*2;

    float c[2][6][4];
    #pragma unroll
    for (int s = 0; s < 2; s++)
        #pragma unroll
        for (int j = 0; j < 6; j++)
            #pragma unroll
            for (int e = 0; e < 4; e++) c[s][j][e] = 0.f;

    #pragma unroll
    for (int ks = 0; ks < 8; ks++) {
        int ka = ks*16 + kq;
        uint32_t a0h0 = *(const uint32_t*)&Ahi[mA*APITCH + ka];
        uint32_t a0h1 = *(const uint32_t*)&Ahi[(mA+8)*APITCH + ka];
        uint32_t a0h2 = *(const uint32_t*)&Ahi[mA*APITCH + ka + 8];
        uint32_t a0h3 = *(const uint32_t*)&Ahi[(mA+8)*APITCH + ka + 8];
        uint32_t a0l0 = *(const uint32_t*)&Alo[mA*APITCH + ka];
        uint32_t a0l1 = *(const uint32_t*)&Alo[(mA+8)*APITCH + ka];
        uint32_t a0l2 = *(const uint32_t*)&Alo[mA*APITCH + ka + 8];
        uint32_t a0l3 = *(const uint32_t*)&Alo[(mA+8)*APITCH + ka + 8];
        uint32_t a1h0 = *(const uint32_t*)&Ahi[(mA+16)*APITCH + ka];
        uint32_t a1h1 = *(const uint32_t*)&Ahi[(mA+24)*APITCH + ka];
        uint32_t a1h2 = *(const uint32_t*)&Ahi[(mA+16)*APITCH + ka + 8];
        uint32_t a1h3 = *(const uint32_t*)&Ahi[(mA+24)*APITCH + ka + 8];
        uint32_t a1l0 = *(const uint32_t*)&Alo[(mA+16)*APITCH + ka];
        uint32_t a1l1 = *(const uint32_t*)&Alo[(mA+24)*APITCH + ka];
        uint32_t a1l2 = *(const uint32_t*)&Alo[(mA+16)*APITCH + ka + 8];
        uint32_t a1l3 = *(const uint32_t*)&Alo[(mA+24)*APITCH + ka + 8];
        const uint32_t* bb = g_WhF + ((size_t)(ks*24 + nquad*6)*32 + lane)*2;
        #pragma unroll
        for (int nt = 0; nt < 6; nt++) {
            uint2 b2 = *(const uint2*)(bb + nt*64);
            MMA4(c[0][nt], a0h0, a0h1, a0h2, a0h3, b2.x, b2.y);
            MMA4(c[0][nt], a0l0, a0l1, a0l2, a0l3, b2.x, b2.y);
            MMA4(c[1][nt], a1h0, a1h1, a1h2, a1h3, b2.x, b2.y);
            MMA4(c[1][nt], a1l0, a1l1, a1l2, a1l3, b2.x, b2.y);
        }
    }

    // epilogue: gate triple for d at c[s][dt], c[s][dt+2], c[s][dt+4]
    int u0 = (lane & 3)*2;
    #pragma unroll
    for (int s = 0; s < 2; s++) {
        int rbase = row0 + sp*32 + s*16 + (lane >> 2);
        #pragma unroll
        for (int dt = 0; dt < 2; dt++) {
            int d = nquad*16 + dt*8 + u0;
            float bi0 = bhid[d],       bi1 = bhid[d+1];
            float bf0 = bhid[64 + d],  bf1 = bhid[64 + d + 1];
            float bq0 = bhid[128 + d], bq1 = bhid[128 + d + 1];
            #pragma unroll
            for (int h = 0; h < 2; h++) {
                int row = rbase + h*8;
                float i0 = c[s][dt][h*2]   + bi0, i1 = c[s][dt][h*2+1]   + bi1;
                float f0 = c[s][dt+2][h*2] + bf0, f1 = c[s][dt+2][h*2+1] + bf1;
                float q0 = c[s][dt+4][h*2] + bq0, q1 = c[s][dt+4][h*2+1] + bq1;
                float2 vf, vi;
                vf.x = sigmoidf_(f0);
                vf.y = sigmoidf_(f1);
                vi.x = sigmoidf_(i0) * fmaxf(q0, 0.f);
                vi.y = sigmoidf_(i1) * fmaxf(q1, 0.f);
                *(float2*)&g_fg [(size_t)row*64 + d] = vf;
                *(float2*)&g_igh[(size_t)row*64 + d] = vi;
            }
        }
    }
}

// ================= K7b: GEMM2 via mma.sync + fused output gate ================
// Block: 256 thr (8 warps), M-tile 128. Warp = 32 rows (2 slabs) x 32 cols (nhalf).
__global__ __launch_bounds__(256, 3) void k7b_mma(const float* __restrict__ x,
                                                  const float* __restrict__ bog,
                                                  float* __restrict__ out) {
    extern __shared__ unsigned short smu[];
    unsigned short* Ahi = smu;
    unsigned short* Alo = smu + 128*APITCH;
    int tid = threadIdx.x, lane = tid & 31, wid = tid >> 5;
    int row0 = blockIdx.x * 128;

    convert_A128_256(Ahi, Alo, x, g_cell, row0, tid);
    __syncthreads();

    int sp = wid >> 1, nhalf = wid & 1;     // sp: 0..3 -> rows sp*32..+32
    int mA = sp*32 + (lane >> 2);
    int kq = (lane & 3)*2;

    float c[2][4][4];
    #pragma unroll
    for (int s = 0; s < 2; s++)
        #pragma unroll
        for (int j = 0; j < 4; j++)
            #pragma unroll
            for (int e = 0; e < 4; e++) c[s][j][e] = 0.f;

    #pragma unroll
    for (int ks = 0; ks < 8; ks++) {
        int ka = ks*16 + kq;
        uint32_t a0h0 = *(const uint32_t*)&Ahi[mA*APITCH + ka];
        uint32_t a0h1 = *(const uint32_t*)&Ahi[(mA+8)*APITCH + ka];
        uint32_t a0h2 = *(const uint32_t*)&Ahi[mA*APITCH + ka + 8];
        uint32_t a0h3 = *(const uint32_t*)&Ahi[(mA+8)*APITCH + ka + 8];
        uint32_t a0l0 = *(const uint32_t*)&Alo[mA*APITCH + ka];
        uint32_t a0l1 = *(const uint32_t*)&Alo[(mA+8)*APITCH + ka];
        uint32_t a0l2 = *(const uint32_t*)&Alo[mA*APITCH + ka + 8];
        uint32_t a0l3 = *(const uint32_t*)&Alo[(mA+8)*APITCH + ka + 8];
        uint32_t a1h0 = *(const uint32_t*)&Ahi[(mA+16)*APITCH + ka];
        uint32_t a1h1 = *(const uint32_t*)&Ahi[(mA+24)*APITCH + ka];
        uint32_t a1h2 = *(const uint32_t*)&Ahi[(mA+16)*APITCH + ka + 8];
        uint32_t a1h3 = *(const uint32_t*)&Ahi[(mA+24)*APITCH + ka + 8];
        uint32_t a1l0 = *(const uint32_t*)&Alo[(mA+16)*APITCH + ka];
        uint32_t a1l1 = *(const uint32_t*)&Alo[(mA+24)*APITCH + ka];
        uint32_t a1l2 = *(const uint32_t*)&Alo[(mA+16)*APITCH + ka + 8];
        uint32_t a1l3 = *(const uint32_t*)&Alo[(mA+24)*APITCH + ka + 8];
        const uint32_t* bb = g_WoF + ((size_t)(ks*8 + nhalf*4)*32 + lane)*2;
        #pragma unroll
        for (int nt = 0; nt < 4; nt++) {
            uint2 b2 = *(const uint2*)(bb + nt*64);
            MMA4(c[0][nt], a0h0, a0h1, a0h2, a0h3, b2.x, b2.y);
            MMA4(c[0][nt], a0l0, a0l1, a0l2, a0l3, b2.x, b2.y);
            MMA4(c[1][nt], a1h0, a1h1, a1h2, a1h3, b2.x, b2.y);
            MMA4(c[1][nt], a1l0, a1l1, a1l2, a1l3, b2.x, b2.y);
        }
    }

    int u0 = (lane & 3)*2;
    #pragma unroll
    for (int s = 0; s < 2; s++) {
        int rbase = row0 + sp*32 + s*16 + (lane >> 2);
        #pragma unroll
        for (int nt = 0; nt < 4; nt++) {
            int d = (nhalf*4 + nt)*8 + u0;
            float b0 = bog[d], b1 = bog[d+1];
            #pragma unroll
            for (int h = 0; h < 2; h++) {
                int row = rbase + h*8;
                float2 cv = *(const float2*)&g_cell[(size_t)row*64 + d];
                float2 ov;
                ov.x = sigmoidf_(c[s][nt][h*2]   + b0) * cv.x;
                ov.y = sigmoidf_(c[s][nt][h*2+1] + b1) * cv.y;
                *(float2*)&out[(size_t)row*64 + d] = ov;
            }
        }
    }
}

// ================= launch =====================================================
extern "C" void kernel_launch(void* const* d_in, const int* in_sizes, int n_in,
                              void* d_out, int out_size) {
    const float* x      = (const float*)d_in[0];
    const float* Wh     = (const float*)d_in[1];
    const float* bh     = (const float*)d_in[2];
    const float* Wog    = (const float*)d_in[3];
    const float* bog    = (const float*)d_in[4];
    const float* gamma  = (const float*)d_in[5];
    const float* beta   = (const float*)d_in[6];
    const float* initcx = (const float*)d_in[7];
    float* out = (float*)d_out;

    static bool attr_done = false;
    if (!attr_done) {
        cudaFuncSetAttribute(k4_mma,  cudaFuncAttributeMaxDynamicSharedMemorySize, A64_SMEM_BYTES);
        cudaFuncSetAttribute(k7b_mma, cudaFuncAttributeMaxDynamicSharedMemorySize, A128_SMEM_BYTES);
        attr_done = true;
    }

    kprep_w<<<48, 256>>>(Wh, Wog);
    k1_chunksum<<<BC, 512>>>(x);
    k3_csum_ln<<<BC, 512>>>(x, gamma, beta);
    k4_mma<<<ROWS/64, 256, A64_SMEM_BYTES>>>(x, bh);
    k5_chunkscan<<<BC, 512>>>();
    k7a_cell<<<BC, 512>>>(initcx);
    k7b_mma<<<ROWS/128, 256, A128_SMEM_BYTES>>>(x, bog, out);
}

// round 10
// speedup vs baseline: 1.0910x; 1.0910x over previous
#include <cuda_runtime.h>
#include <cuda_bf16.h>
#include <cuda_fp16.h>
#include <cstdint>

// Problem dims
#define BB 4
#define SS 4096
#define HH 8
#define DD 64
#define HD 512
#define TOK (BB*SS)
#define ROWS (TOK*HH)          // 131072 gemm rows
#define CC 32
#define NC (SS/CC)
#define BC (BB*NC)

// ================= scratch ====================================================
__device__ float g_csum[ROWS*DD];
__device__ float g_fg  [ROWS*DD];
__device__ float g_igh [ROWS*DD];
__device__ float g_cell[ROWS*DD];
__device__ float g_chunksum[BC*HD];
__device__ float g_A [BC*HD];
__device__ float g_Bv[BC*HD];
__device__ int   g_flag1[BC];
__device__ int   g_flag2[BC];
// W pre-packed in mma B-fragment order: [ks][nt][lane][2] u32 (fp16x2 each)
__device__ uint32_t g_WhF[12288];   // GEMM1: 8 ks * 24 nt * 32 * 2
__device__ uint32_t g_WoF[4096];    // GEMM2: 8 ks * 8 nt * 32 * 2

// ================= helpers ====================================================
__device__ __forceinline__ float sigmoidf_(float v) { return 1.f / (1.f + __expf(-v)); }

__device__ __forceinline__ void split_f16(float v, unsigned short& hi, unsigned short& lo) {
    __half h = __float2half_rn(v);
    __half l = __float2half_rn(v - __half2float(h));
    hi = __half_as_ushort(h);
    lo = __half_as_ushort(l);
}

#define MMA4(c, a0,a1,a2,a3, b0,b1) \
    asm volatile("mma.sync.aligned.m16n8k16.row.col.f32.f16.f16.f32 " \
        "{%0,%1,%2,%3}, {%4,%5,%6,%7}, {%8,%9}, {%0,%1,%2,%3};" \
        : "+f"((c)[0]),"+f"((c)[1]),"+f"((c)[2]),"+f"((c)[3]) \
        : "r"(a0),"r"(a1),"r"(a2),"r"(a3),"r"(b0),"r"(b1))

// ================= prep: W -> B-fragment images + flag reset ==================
__global__ void kprep_w(const float* __restrict__ Wh, const float* __restrict__ Wog) {
    int t = blockIdx.x * blockDim.x + threadIdx.x;
    int stride = gridDim.x * blockDim.x;
    for (int i = t; i < BC; i += stride) { g_flag1[i] = 0; g_flag2[i] = 0; }
    for (int idx = t; idx < 12288; idx += stride) {
        int reg  = idx & 1;
        int lane = (idx >> 1) & 31;
        int nt   = (idx >> 6) % 24;
        int ks   = (idx >> 6) / 24;
        int nquad = nt / 6, ntl = nt % 6;
        int gate = ntl >> 1, dt = ntl & 1;
        int d = nquad*16 + dt*8 + (lane >> 2);
        int n = gate*64 + d;
        int k0 = ks*16 + (lane & 3)*2 + reg*8;
        unsigned short h0 = __half_as_ushort(__float2half_rn(Wh[(size_t)k0*192 + n]));
        unsigned short h1 = __half_as_ushort(__float2half_rn(Wh[(size_t)(k0+1)*192 + n]));
        g_WhF[idx] = (uint32_t)h0 | ((uint32_t)h1 << 16);
    }
    for (int idx = t; idx < 4096; idx += stride) {
        int reg  = idx & 1;
        int lane = (idx >> 1) & 31;
        int nt   = (idx >> 6) % 8;
        int ks   = (idx >> 6) / 8;
        int n = nt*8 + (lane >> 2);
        int k0 = ks*16 + (lane & 3)*2 + reg*8;
        unsigned short h0 = __half_as_ushort(__float2half_rn(Wog[(size_t)k0*64 + n]));
        unsigned short h1 = __half_as_ushort(__float2half_rn(Wog[(size_t)(k0+1)*64 + n]));
        g_WoF[idx] = (uint32_t)h0 | ((uint32_t)h1 << 16);
    }
}

// ================= K3: chunk-sum + decoupled lookback + cumsum + LayerNorm ====
__global__ __launch_bounds__(512) void k3_csum_ln(const float* __restrict__ x,
                                                  const float* __restrict__ gamma,
                                                  const float* __restrict__ beta) {
    int bc = blockIdx.x;
    int b = bc / NC, c = bc % NC;
    int tid = threadIdx.x;
    int warp = tid >> 5, lane = tid & 31;
    __shared__ float sm_s[16][33];
    __shared__ float sm_q[16][33];
    __shared__ float sm_mean[32], sm_inv[32];

    size_t base = ((size_t)(b*SS + c*CC))*HD + tid;
    const float* px = x + base;

    // pass 0: own chunk sum, publish
    float sown = 0.f;
    #pragma unroll
    for (int i = 0; i < CC; i++) sown += px[(size_t)i*HD];
    g_chunksum[(size_t)bc*HD + tid] = sown;
    __threadfence();
    __syncthreads();
    if (tid == 0) atomicExch(&g_flag1[bc], 1);

    // lookback: wait for predecessors, then sum their chunk sums
    if (tid < c) {
        while (atomicAdd(&g_flag1[b*NC + tid], 0) == 0) __nanosleep(64);
        __threadfence();
    }
    __syncthreads();

    float run = 0.f;
    {
        const float* pcs = g_chunksum + (size_t)b*NC*HD + tid;
        int j = 0;
        for (; j + 4 <= c; j += 4)
            run += pcs[(size_t)(j+0)*HD] + pcs[(size_t)(j+1)*HD]
                 + pcs[(size_t)(j+2)*HD] + pcs[(size_t)(j+3)*HD];
        for (; j < c; j++) run += pcs[(size_t)j*HD];
    }

    float ga = gamma[tid], be = beta[tid];
    float* pc = g_csum + base;

    // phase 1: per-token per-warp partial (sum, sumsq)
    float r1 = run;
    #pragma unroll
    for (int i = 0; i < CC; i++) {
        float val = r1;
        r1 += px[(size_t)i*HD];
        float s = val, q = val*val;
        #pragma unroll
        for (int o = 16; o; o >>= 1) {
            s += __shfl_xor_sync(0xffffffffu, s, o);
            q += __shfl_xor_sync(0xffffffffu, q, o);
        }
        if (lane == 0) { sm_s[warp][i] = s; sm_q[warp][i] = q; }
    }
    __syncthreads();

    // phase 2: reduce 16 warp-partials per token
    {
        int t = tid >> 4, k = tid & 15;
        float s = sm_s[k][t], q = sm_q[k][t];
        #pragma unroll
        for (int o = 8; o; o >>= 1) {
            s += __shfl_xor_sync(0xffffffffu, s, o);
            q += __shfl_xor_sync(0xffffffffu, q, o);
        }
        if (k == 0) {
            float m = s * (1.f/512.f);
            float v = q * (1.f/512.f) - m*m;
            sm_mean[t] = m;
            sm_inv[t]  = rsqrtf(v + 1e-5f);
        }
    }
    __syncthreads();

    // phase 3: rewalk and write normalized
    float r2 = run;
    #pragma unroll
    for (int i = 0; i < CC; i++) {
        float val = r2;
        r2 += px[(size_t)i*HD];
        pc[(size_t)i*HD] = (val - sm_mean[i]) * sm_inv[i] * ga + be;
    }
}

// ================= K7a: chunk state + decoupled lookback + replay cell ========
__global__ __launch_bounds__(512) void k7a_cell(const float* __restrict__ initcx) {
    int bc = blockIdx.x;
    int b = bc / NC, c = bc % NC;
    int tid = threadIdx.x;

    size_t base = ((size_t)(b*SS + c*CC))*HD + tid;
    const float* pf = g_fg + base;
    const float* pg = g_igh + base;

    // pass 0: own chunk affine state (a, bv), publish
    float a = 1.f, bv = 0.f;
    #pragma unroll
    for (int i = 0; i < CC; i++) {
        float f = pf[(size_t)i*HD], g = pg[(size_t)i*HD];
        a *= f;
        bv = bv * f + g;
    }
    g_A [(size_t)bc*HD + tid] = a;
    g_Bv[(size_t)bc*HD + tid] = bv;
    __threadfence();
    __syncthreads();
    if (tid == 0) atomicExch(&g_flag2[bc], 1);

    // lookback
    if (tid < c) {
        while (atomicAdd(&g_flag2[b*NC + tid], 0) == 0) __nanosleep(64);
        __threadfence();
    }
    __syncthreads();

    float carry = initcx[tid];
    {
        const float* pA = g_A  + (size_t)b*NC*HD + tid;
        const float* pB = g_Bv + (size_t)b*NC*HD + tid;
        #pragma unroll 4
        for (int j = 0; j < c; j++)
            carry = pA[(size_t)j*HD] * carry + pB[(size_t)j*HD];
    }

    // replay
    float* pcell = g_cell + base;
    float cell = carry;
    #pragma unroll
    for (int i = 0; i < CC; i++) {
        cell = pf[(size_t)i*HD] * cell + pg[(size_t)i*HD];
        pcell[(size_t)i*HD] = cell;
    }
}

// ================= A tile converts: f32 -> fp16 hi/lo in SMEM =================
#define APITCH 136
#define A64_SMEM_BYTES (2*64*APITCH*2)    // 34816
#define A128_SMEM_BYTES (2*128*APITCH*2)  // 69632

// 64-row tile, 512 threads: r = tid>>3, k-eighth = tid&7 (16 k each).
__device__ __forceinline__ void convert_A64(unsigned short* Ahi, unsigned short* Alo,
                                            const float* __restrict__ x,
                                            const float* __restrict__ other,
                                            int row0, int tid) {
    int r = tid >> 3;
    int q = tid & 7;
    const float* src = (q < 4)
        ? (x     + (size_t)(row0 + r)*64 + q*16)
        : (other + (size_t)(row0 + r)*64 + (q-4)*16);
    int kbase = q*16;
    const float4* p4 = (const float4*)src;
    #pragma unroll
    for (int i = 0; i < 4; i++) {
        float4 v = p4[i];
        unsigned short h0,l0,h1,l1,h2,l2,h3,l3;
        split_f16(v.x, h0, l0);
        split_f16(v.y, h1, l1);
        split_f16(v.z, h2, l2);
        split_f16(v.w, h3, l3);
        int k = kbase + i*4;
        *(uint32_t*)&Ahi[r*APITCH + k]     = (uint32_t)h0 | ((uint32_t)h1 << 16);
        *(uint32_t*)&Ahi[r*APITCH + k + 2] = (uint32_t)h2 | ((uint32_t)h3 << 16);
        *(uint32_t*)&Alo[r*APITCH + k]     = (uint32_t)l0 | ((uint32_t)l1 << 16);
        *(uint32_t*)&Alo[r*APITCH + k + 2] = (uint32_t)l2 | ((uint32_t)l3 << 16);
    }
}

// 128-row tile, 512 threads: r = tid>>2, k-quarter = tid&3 (32 k each).
__device__ __forceinline__ void convert_A128(unsigned short* Ahi, unsigned short* Alo,
                                             const float* __restrict__ x,
                                             const float* __restrict__ other,
                                             int row0, int tid) {
    int r = tid >> 2;
    int q = tid & 3;
    const float* src = (q < 2)
        ? (x     + (size_t)(row0 + r)*64 + q*32)
        : (other + (size_t)(row0 + r)*64 + (q-2)*32);
    int kbase = q*32;
    const float4* p4 = (const float4*)src;
    #pragma unroll
    for (int i = 0; i < 8; i++) {
        float4 v = p4[i];
        unsigned short h0,l0,h1,l1,h2,l2,h3,l3;
        split_f16(v.x, h0, l0);
        split_f16(v.y, h1, l1);
        split_f16(v.z, h2, l2);
        split_f16(v.w, h3, l3);
        int k = kbase + i*4;
        *(uint32_t*)&Ahi[r*APITCH + k]     = (uint32_t)h0 | ((uint32_t)h1 << 16);
        *(uint32_t*)&Ahi[r*APITCH + k + 2] = (uint32_t)h2 | ((uint32_t)h3 << 16);
        *(uint32_t*)&Alo[r*APITCH + k]     = (uint32_t)l0 | ((uint32_t)l1 << 16);
        *(uint32_t*)&Alo[r*APITCH + k + 2] = (uint32_t)l2 | ((uint32_t)l3 << 16);
    }
}

// ================= K4: GEMM1 via mma.sync + fused gates (R8 config) ===========
// Block: 512 thr (16 warps), M-tile 64. Warp = slab(4)*16 rows x nquad(4)*48 cols.
__global__ __launch_bounds__(512, 2) void k4_mma(const float* __restrict__ x,
                                                 const float* __restrict__ bhid) {
    extern __shared__ unsigned short smu[];
    unsigned short* Ahi = smu;
    unsigned short* Alo = smu + 64*APITCH;
    int tid = threadIdx.x, lane = tid & 31, wid = tid >> 5;
    int row0 = blockIdx.x * 64;

    convert_A64(Ahi, Alo, x, g_csum, row0, tid);
    __syncthreads();

    int slab = wid >> 2, nquad = wid & 3;
    int m0 = slab*16 + (lane >> 2);
    int kq = (lane & 3)*2;

    float c[6][4];
    #pragma unroll
    for (int j = 0; j < 6; j++)
        #pragma unroll
        for (int e = 0; e < 4; e++) c[j][e] = 0.f;

    #pragma unroll
    for (int ks = 0; ks < 8; ks++) {
        int ka = ks*16 + kq;
        uint32_t ah0 = *(const uint32_t*)&Ahi[m0*APITCH + ka];
        uint32_t ah1 = *(const uint32_t*)&Ahi[(m0+8)*APITCH + ka];
        uint32_t ah2 = *(const uint32_t*)&Ahi[m0*APITCH + ka + 8];
        uint32_t ah3 = *(const uint32_t*)&Ahi[(m0+8)*APITCH + ka + 8];
        uint32_t al0 = *(const uint32_t*)&Alo[m0*APITCH + ka];
        uint32_t al1 = *(const uint32_t*)&Alo[(m0+8)*APITCH + ka];
        uint32_t al2 = *(const uint32_t*)&Alo[m0*APITCH + ka + 8];
        uint32_t al3 = *(const uint32_t*)&Alo[(m0+8)*APITCH + ka + 8];
        const uint32_t* bb = g_WhF + ((size_t)(ks*24 + nquad*6)*32 + lane)*2;
        #pragma unroll
        for (int nt = 0; nt < 6; nt++) {
            uint2 b2 = *(const uint2*)(bb + nt*64);
            MMA4(c[nt], ah0, ah1, ah2, ah3, b2.x, b2.y);
            MMA4(c[nt], al0, al1, al2, al3, b2.x, b2.y);
        }
    }

    // epilogue: gate triple for d at c[dt], c[dt+2], c[dt+4]
    int u0 = (lane & 3)*2;
    int rbase = row0 + slab*16 + (lane >> 2);
    #pragma unroll
    for (int dt = 0; dt < 2; dt++) {
        int d = nquad*16 + dt*8 + u0;
        float bi0 = bhid[d],       bi1 = bhid[d+1];
        float bf0 = bhid[64 + d],  bf1 = bhid[64 + d + 1];
        float bq0 = bhid[128 + d], bq1 = bhid[128 + d + 1];
        #pragma unroll
        for (int h = 0; h < 2; h++) {
            int row = rbase + h*8;
            float i0 = c[dt][h*2]   + bi0, i1 = c[dt][h*2+1]   + bi1;
            float f0 = c[dt+2][h*2] + bf0, f1 = c[dt+2][h*2+1] + bf1;
            float q0 = c[dt+4][h*2] + bq0, q1 = c[dt+4][h*2+1] + bq1;
            float2 vf, vi;
            vf.x = sigmoidf_(f0);
            vf.y = sigmoidf_(f1);
            vi.x = sigmoidf_(i0) * fmaxf(q0, 0.f);
            vi.y = sigmoidf_(i1) * fmaxf(q1, 0.f);
            *(float2*)&g_fg [(size_t)row*64 + d] = vf;
            *(float2*)&g_igh[(size_t)row*64 + d] = vi;
        }
    }
}

// ================= K7b: GEMM2 via mma.sync + fused output gate (R8 config) ====
// Block: 512 thr (16 warps), M-tile 128. Warp = slab(8)*16 rows x nhalf(2)*32 cols.
__global__ __launch_bounds__(512, 2) void k7b_mma(const float* __restrict__ x,
                                                  const float* __restrict__ bog,
                                                  float* __restrict__ out) {
    extern __shared__ unsigned short smu[];
    unsigned short* Ahi = smu;
    unsigned short* Alo = smu + 128*APITCH;
    int tid = threadIdx.x, lane = tid & 31, wid = tid >> 5;
    int row0 = blockIdx.x * 128;

    convert_A128(Ahi, Alo, x, g_cell, row0, tid);
    __syncthreads();

    int slab = wid >> 1, nhalf = wid & 1;
    int m0 = slab*16 + (lane >> 2);
    int kq = (lane & 3)*2;

    float c[4][4];
    #pragma unroll
    for (int j = 0; j < 4; j++)
        #pragma unroll
        for (int e = 0; e < 4; e++) c[j][e] = 0.f;

    #pragma unroll
    for (int ks = 0; ks < 8; ks++) {
        int ka = ks*16 + kq;
        uint32_t ah0 = *(const uint32_t*)&Ahi[m0*APITCH + ka];
        uint32_t ah1 = *(const uint32_t*)&Ahi[(m0+8)*APITCH + ka];
        uint32_t ah2 = *(const uint32_t*)&Ahi[m0*APITCH + ka + 8];
        uint32_t ah3 = *(const uint32_t*)&Ahi[(m0+8)*APITCH + ka + 8];
        uint32_t al0 = *(const uint32_t*)&Alo[m0*APITCH + ka];
        uint32_t al1 = *(const uint32_t*)&Alo[(m0+8)*APITCH + ka];
        uint32_t al2 = *(const uint32_t*)&Alo[m0*APITCH + ka + 8];
        uint32_t al3 = *(const uint32_t*)&Alo[(m0+8)*APITCH + ka + 8];
        const uint32_t* bb = g_WoF + ((size_t)(ks*8 + nhalf*4)*32 + lane)*2;
        #pragma unroll
        for (int nt = 0; nt < 4; nt++) {
            uint2 b2 = *(const uint2*)(bb + nt*64);
            MMA4(c[nt], ah0, ah1, ah2, ah3, b2.x, b2.y);
            MMA4(c[nt], al0, al1, al2, al3, b2.x, b2.y);
        }
    }

    int u0 = (lane & 3)*2;
    int rbase = row0 + slab*16 + (lane >> 2);
    #pragma unroll
    for (int nt = 0; nt < 4; nt++) {
        int d = (nhalf*4 + nt)*8 + u0;
        float b0 = bog[d], b1 = bog[d+1];
        #pragma unroll
        for (int h = 0; h < 2; h++) {
            int row = rbase + h*8;
            float2 cv = *(const float2*)&g_cell[(size_t)row*64 + d];
            float2 ov;
            ov.x = sigmoidf_(c[nt][h*2]   + b0) * cv.x;
            ov.y = sigmoidf_(c[nt][h*2+1] + b1) * cv.y;
            *(float2*)&out[(size_t)row*64 + d] = ov;
        }
    }
}

// ================= launch =====================================================
extern "C" void kernel_launch(void* const* d_in, const int* in_sizes, int n_in,
                              void* d_out, int out_size) {
    const float* x      = (const float*)d_in[0];
    const float* Wh     = (const float*)d_in[1];
    const float* bh     = (const float*)d_in[2];
    const float* Wog    = (const float*)d_in[3];
    const float* bog    = (const float*)d_in[4];
    const float* gamma  = (const float*)d_in[5];
    const float* beta   = (const float*)d_in[6];
    const float* initcx = (const float*)d_in[7];
    float* out = (float*)d_out;

    static bool attr_done = false;
    if (!attr_done) {
        cudaFuncSetAttribute(k4_mma,  cudaFuncAttributeMaxDynamicSharedMemorySize, A64_SMEM_BYTES);
        cudaFuncSetAttribute(k7b_mma, cudaFuncAttributeMaxDynamicSharedMemorySize, A128_SMEM_BYTES);
        attr_done = true;
    }

    kprep_w<<<48, 256>>>(Wh, Wog);
    k3_csum_ln<<<BC, 512>>>(x, gamma, beta);
    k4_mma<<<ROWS/64, 512, A64_SMEM_BYTES>>>(x, bh);
    k7a_cell<<<BC, 512>>>(initcx);
    k7b_mma<<<ROWS/128, 512, A128_SMEM_BYTES>>>(x, bog, out);
}

// round 11
// speedup vs baseline: 1.1912x; 1.0918x over previous
#include <cuda_runtime.h>
#include <cuda_bf16.h>
#include <cuda_fp16.h>
#include <cstdint>

// Problem dims
#define BB 4
#define SS 4096
#define HH 8
#define DD 64
#define HD 512
#define TOK (BB*SS)
#define ROWS (TOK*HH)          // 131072 gemm rows
#define CC 32
#define NC (SS/CC)
#define BC (BB*NC)

// ================= scratch ====================================================
__device__ float g_csum[ROWS*DD];
__device__ float g_fg  [ROWS*DD];
__device__ float g_igh [ROWS*DD];
__device__ float g_cell[ROWS*DD];
__device__ float g_chunksum[BC*HD];
__device__ float g_A [BC*HD];
__device__ float g_Bv[BC*HD];
__device__ int   g_flag1[BC];
__device__ int   g_flag2[BC];
// W pre-packed in mma B-fragment order: [ks][nt][lane][2] u32 (fp16x2 each)
__device__ uint32_t g_WhF[12288];   // GEMM1: 8 ks * 24 nt * 32 * 2
__device__ uint32_t g_WoF[4096];    // GEMM2: 8 ks * 8 nt * 32 * 2

// ================= helpers ====================================================
__device__ __forceinline__ float sigmoidf_(float v) { return 1.f / (1.f + __expf(-v)); }

#define MMA4(c, a0,a1,a2,a3, b0,b1) \
    asm volatile("mma.sync.aligned.m16n8k16.row.col.f32.f16.f16.f32 " \
        "{%0,%1,%2,%3}, {%4,%5,%6,%7}, {%8,%9}, {%0,%1,%2,%3};" \
        : "+f"((c)[0]),"+f"((c)[1]),"+f"((c)[2]),"+f"((c)[3]) \
        : "r"(a0),"r"(a1),"r"(a2),"r"(a3),"r"(b0),"r"(b1))

// ================= prep: W -> B-fragment images + flag reset ==================
__global__ void kprep_w(const float* __restrict__ Wh, const float* __restrict__ Wog) {
    int t = blockIdx.x * blockDim.x + threadIdx.x;
    int stride = gridDim.x * blockDim.x;
    for (int i = t; i < BC; i += stride) { g_flag1[i] = 0; g_flag2[i] = 0; }
    for (int idx = t; idx < 12288; idx += stride) {
        int reg  = idx & 1;
        int lane = (idx >> 1) & 31;
        int nt   = (idx >> 6) % 24;
        int ks   = (idx >> 6) / 24;
        int nquad = nt / 6, ntl = nt % 6;
        int gate = ntl >> 1, dt = ntl & 1;
        int d = nquad*16 + dt*8 + (lane >> 2);
        int n = gate*64 + d;
        int k0 = ks*16 + (lane & 3)*2 + reg*8;
        unsigned short h0 = __half_as_ushort(__float2half_rn(Wh[(size_t)k0*192 + n]));
        unsigned short h1 = __half_as_ushort(__float2half_rn(Wh[(size_t)(k0+1)*192 + n]));
        g_WhF[idx] = (uint32_t)h0 | ((uint32_t)h1 << 16);
    }
    for (int idx = t; idx < 4096; idx += stride) {
        int reg  = idx & 1;
        int lane = (idx >> 1) & 31;
        int nt   = (idx >> 6) % 8;
        int ks   = (idx >> 6) / 8;
        int n = nt*8 + (lane >> 2);
        int k0 = ks*16 + (lane & 3)*2 + reg*8;
        unsigned short h0 = __half_as_ushort(__float2half_rn(Wog[(size_t)k0*64 + n]));
        unsigned short h1 = __half_as_ushort(__float2half_rn(Wog[(size_t)(k0+1)*64 + n]));
        g_WoF[idx] = (uint32_t)h0 | ((uint32_t)h1 << 16);
    }
}

// ================= K3: chunk-sum + decoupled lookback + cumsum + LayerNorm ====
__global__ __launch_bounds__(512) void k3_csum_ln(const float* __restrict__ x,
                                                  const float* __restrict__ gamma,
                                                  const float* __restrict__ beta) {
    int bc = blockIdx.x;
    int b = bc / NC, c = bc % NC;
    int tid = threadIdx.x;
    int warp = tid >> 5, lane = tid & 31;
    __shared__ float sm_s[16][33];
    __shared__ float sm_q[16][33];
    __shared__ float sm_mean[32], sm_inv[32];

    size_t base = ((size_t)(b*SS + c*CC))*HD + tid;
    const float* px = x + base;

    // pass 0: own chunk sum, publish
    float sown = 0.f;
    #pragma unroll
    for (int i = 0; i < CC; i++) sown += px[(size_t)i*HD];
    g_chunksum[(size_t)bc*HD + tid] = sown;
    __threadfence();
    __syncthreads();
    if (tid == 0) atomicExch(&g_flag1[bc], 1);

    // lookback: wait for predecessors, then sum their chunk sums
    if (tid < c) {
        while (atomicAdd(&g_flag1[b*NC + tid], 0) == 0) __nanosleep(64);
        __threadfence();
    }
    __syncthreads();

    float run = 0.f;
    {
        const float* pcs = g_chunksum + (size_t)b*NC*HD + tid;
        int j = 0;
        for (; j + 4 <= c; j += 4)
            run += pcs[(size_t)(j+0)*HD] + pcs[(size_t)(j+1)*HD]
                 + pcs[(size_t)(j+2)*HD] + pcs[(size_t)(j+3)*HD];
        for (; j < c; j++) run += pcs[(size_t)j*HD];
    }

    float ga = gamma[tid], be = beta[tid];
    float* pc = g_csum + base;

    // phase 1: per-token per-warp partial (sum, sumsq)
    float r1 = run;
    #pragma unroll
    for (int i = 0; i < CC; i++) {
        float val = r1;
        r1 += px[(size_t)i*HD];
        float s = val, q = val*val;
        #pragma unroll
        for (int o = 16; o; o >>= 1) {
            s += __shfl_xor_sync(0xffffffffu, s, o);
            q += __shfl_xor_sync(0xffffffffu, q, o);
        }
        if (lane == 0) { sm_s[warp][i] = s; sm_q[warp][i] = q; }
    }
    __syncthreads();

    // phase 2: reduce 16 warp-partials per token
    {
        int t = tid >> 4, k = tid & 15;
        float s = sm_s[k][t], q = sm_q[k][t];
        #pragma unroll
        for (int o = 8; o; o >>= 1) {
            s += __shfl_xor_sync(0xffffffffu, s, o);
            q += __shfl_xor_sync(0xffffffffu, q, o);
        }
        if (k == 0) {
            float m = s * (1.f/512.f);
            float v = q * (1.f/512.f) - m*m;
            sm_mean[t] = m;
            sm_inv[t]  = rsqrtf(v + 1e-5f);
        }
    }
    __syncthreads();

    // phase 3: rewalk and write normalized
    float r2 = run;
    #pragma unroll
    for (int i = 0; i < CC; i++) {
        float val = r2;
        r2 += px[(size_t)i*HD];
        pc[(size_t)i*HD] = (val - sm_mean[i]) * sm_inv[i] * ga + be;
    }
}

// ================= K7a: chunk state + decoupled lookback + replay cell ========
__global__ __launch_bounds__(512) void k7a_cell(const float* __restrict__ initcx) {
    int bc = blockIdx.x;
    int b = bc / NC, c = bc % NC;
    int tid = threadIdx.x;

    size_t base = ((size_t)(b*SS + c*CC))*HD + tid;
    const float* pf = g_fg + base;
    const float* pg = g_igh + base;

    // pass 0: own chunk affine state (a, bv), publish
    float a = 1.f, bv = 0.f;
    #pragma unroll
    for (int i = 0; i < CC; i++) {
        float f = pf[(size_t)i*HD], g = pg[(size_t)i*HD];
        a *= f;
        bv = bv * f + g;
    }
    g_A [(size_t)bc*HD + tid] = a;
    g_Bv[(size_t)bc*HD + tid] = bv;
    __threadfence();
    __syncthreads();
    if (tid == 0) atomicExch(&g_flag2[bc], 1);

    // lookback
    if (tid < c) {
        while (atomicAdd(&g_flag2[b*NC + tid], 0) == 0) __nanosleep(64);
        __threadfence();
    }
    __syncthreads();

    // batched fold: 8-wide register prefetch breaks the dependent-load chain
    float carry = initcx[tid];
    {
        const float* pA = g_A  + (size_t)b*NC*HD + tid;
        const float* pB = g_Bv + (size_t)b*NC*HD + tid;
        int j = 0;
        for (; j + 8 <= c; j += 8) {
            float av[8], bw[8];
            #pragma unroll
            for (int u = 0; u < 8; u++) {
                av[u] = pA[(size_t)(j+u)*HD];
                bw[u] = pB[(size_t)(j+u)*HD];
            }
            #pragma unroll
            for (int u = 0; u < 8; u++)
                carry = av[u] * carry + bw[u];
        }
        for (; j < c; j++)
            carry = pA[(size_t)j*HD] * carry + pB[(size_t)j*HD];
    }

    // replay
    float* pcell = g_cell + base;
    float cell = carry;
    #pragma unroll
    for (int i = 0; i < CC; i++) {
        cell = pf[(size_t)i*HD] * cell + pg[(size_t)i*HD];
        pcell[(size_t)i*HD] = cell;
    }
}

// ================= A tile converts: f32 -> fp16 in SMEM =======================
#define APITCH 136
#define A64_SMEM_BYTES (64*APITCH*2)      // 17408
#define A128_SMEM_BYTES (128*APITCH*2)    // 34816

// 64-row tile, 512 threads: r = tid>>3, k-eighth = tid&7 (16 k each).
__device__ __forceinline__ void convert_A64(unsigned short* Ah,
                                            const float* __restrict__ x,
                                            const float* __restrict__ other,
                                            int row0, int tid) {
    int r = tid >> 3;
    int q = tid & 7;
    const float* src = (q < 4)
        ? (x     + (size_t)(row0 + r)*64 + q*16)
        : (other + (size_t)(row0 + r)*64 + (q-4)*16);
    int kbase = q*16;
    const float4* p4 = (const float4*)src;
    #pragma unroll
    for (int i = 0; i < 4; i++) {
        float4 v = p4[i];
        unsigned short h0 = __half_as_ushort(__float2half_rn(v.x));
        unsigned short h1 = __half_as_ushort(__float2half_rn(v.y));
        unsigned short h2 = __half_as_ushort(__float2half_rn(v.z));
        unsigned short h3 = __half_as_ushort(__float2half_rn(v.w));
        int k = kbase + i*4;
        *(uint32_t*)&Ah[r*APITCH + k]     = (uint32_t)h0 | ((uint32_t)h1 << 16);
        *(uint32_t*)&Ah[r*APITCH + k + 2] = (uint32_t)h2 | ((uint32_t)h3 << 16);
    }
}

// 128-row tile, 512 threads: r = tid>>2, k-quarter = tid&3 (32 k each).
__device__ __forceinline__ void convert_A128(unsigned short* Ah,
                                             const float* __restrict__ x,
                                             const float* __restrict__ other,
                                             int row0, int tid) {
    int r = tid >> 2;
    int q = tid & 3;
    const float* src = (q < 2)
        ? (x     + (size_t)(row0 + r)*64 + q*32)
        : (other + (size_t)(row0 + r)*64 + (q-2)*32);
    int kbase = q*32;
    const float4* p4 = (const float4*)src;
    #pragma unroll
    for (int i = 0; i < 8; i++) {
        float4 v = p4[i];
        unsigned short h0 = __half_as_ushort(__float2half_rn(v.x));
        unsigned short h1 = __half_as_ushort(__float2half_rn(v.y));
        unsigned short h2 = __half_as_ushort(__float2half_rn(v.z));
        unsigned short h3 = __half_as_ushort(__float2half_rn(v.w));
        int k = kbase + i*4;
        *(uint32_t*)&Ah[r*APITCH + k]     = (uint32_t)h0 | ((uint32_t)h1 << 16);
        *(uint32_t*)&Ah[r*APITCH + k + 2] = (uint32_t)h2 | ((uint32_t)h3 << 16);
    }
}

// ================= K4: GEMM1 via mma.sync + fused gates =======================
// Block: 512 thr (16 warps), M-tile 64. Warp = slab(4)*16 rows x nquad(4)*48 cols.
__global__ __launch_bounds__(512, 2) void k4_mma(const float* __restrict__ x,
                                                 const float* __restrict__ bhid) {
    extern __shared__ unsigned short smu[];
    unsigned short* Ah = smu;
    int tid = threadIdx.x, lane = tid & 31, wid = tid >> 5;
    int row0 = blockIdx.x * 64;

    convert_A64(Ah, x, g_csum, row0, tid);
    __syncthreads();

    int slab = wid >> 2, nquad = wid & 3;
    int m0 = slab*16 + (lane >> 2);
    int kq = (lane & 3)*2;

    float c[6][4];
    #pragma unroll
    for (int j = 0; j < 6; j++)
        #pragma unroll
        for (int e = 0; e < 4; e++) c[j][e] = 0.f;

    #pragma unroll
    for (int ks = 0; ks < 8; ks++) {
        int ka = ks*16 + kq;
        uint32_t a0 = *(const uint32_t*)&Ah[m0*APITCH + ka];
        uint32_t a1 = *(const uint32_t*)&Ah[(m0+8)*APITCH + ka];
        uint32_t a2 = *(const uint32_t*)&Ah[m0*APITCH + ka + 8];
        uint32_t a3 = *(const uint32_t*)&Ah[(m0+8)*APITCH + ka + 8];
        const uint32_t* bb = g_WhF + ((size_t)(ks*24 + nquad*6)*32 + lane)*2;
        #pragma unroll
        for (int nt = 0; nt < 6; nt++) {
            uint2 b2 = *(const uint2*)(bb + nt*64);
            MMA4(c[nt], a0, a1, a2, a3, b2.x, b2.y);
        }
    }

    // epilogue: gate triple for d at c[dt], c[dt+2], c[dt+4]
    int u0 = (lane & 3)*2;
    int rbase = row0 + slab*16 + (lane >> 2);
    #pragma unroll
    for (int dt = 0; dt < 2; dt++) {
        int d = nquad*16 + dt*8 + u0;
        float bi0 = bhid[d],       bi1 = bhid[d+1];
        float bf0 = bhid[64 + d],  bf1 = bhid[64 + d + 1];
        float bq0 = bhid[128 + d], bq1 = bhid[128 + d + 1];
        #pragma unroll
        for (int h = 0; h < 2; h++) {
            int row = rbase + h*8;
            float i0 = c[dt][h*2]   + bi0, i1 = c[dt][h*2+1]   + bi1;
            float f0 = c[dt+2][h*2] + bf0, f1 = c[dt+2][h*2+1] + bf1;
            float q0 = c[dt+4][h*2] + bq0, q1 = c[dt+4][h*2+1] + bq1;
            float2 vf, vi;
            vf.x = sigmoidf_(f0);
            vf.y = sigmoidf_(f1);
            vi.x = sigmoidf_(i0) * fmaxf(q0, 0.f);
            vi.y = sigmoidf_(i1) * fmaxf(q1, 0.f);
            *(float2*)&g_fg [(size_t)row*64 + d] = vf;
            *(float2*)&g_igh[(size_t)row*64 + d] = vi;
        }
    }
}

// ================= K7b: GEMM2 via mma.sync + fused output gate ================
// Block: 512 thr (16 warps), M-tile 128. Warp = slab(8)*16 rows x nhalf(2)*32 cols.
__global__ __launch_bounds__(512, 2) void k7b_mma(const float* __restrict__ x,
                                                  const float* __restrict__ bog,
                                                  float* __restrict__ out) {
    extern __shared__ unsigned short smu[];
    unsigned short* Ah = smu;
    int tid = threadIdx.x, lane = tid & 31, wid = tid >> 5;
    int row0 = blockIdx.x * 128;

    convert_A128(Ah, x, g_cell, row0, tid);
    __syncthreads();

    int slab = wid >> 1, nhalf = wid & 1;
    int m0 = slab*16 + (lane >> 2);
    int kq = (lane & 3)*2;

    float c[4][4];
    #pragma unroll
    for (int j = 0; j < 4; j++)
        #pragma unroll
        for (int e = 0; e < 4; e++) c[j][e] = 0.f;

    #pragma unroll
    for (int ks = 0; ks < 8; ks++) {
        int ka = ks*16 + kq;
        uint32_t a0 = *(const uint32_t*)&Ah[m0*APITCH + ka];
        uint32_t a1 = *(const uint32_t*)&Ah[(m0+8)*APITCH + ka];
        uint32_t a2 = *(const uint32_t*)&Ah[m0*APITCH + ka + 8];
        uint32_t a3 = *(const uint32_t*)&Ah[(m0+8)*APITCH + ka + 8];
        const uint32_t* bb = g_WoF + ((size_t)(ks*8 + nhalf*4)*32 + lane)*2;
        #pragma unroll
        for (int nt = 0; nt < 4; nt++) {
            uint2 b2 = *(const uint2*)(bb + nt*64);
            MMA4(c[nt], a0, a1, a2, a3, b2.x, b2.y);
        }
    }

    int u0 = (lane & 3)*2;
    int rbase = row0 + slab*16 + (lane >> 2);
    #pragma unroll
    for (int nt = 0; nt < 4; nt++) {
        int d = (nhalf*4 + nt)*8 + u0;
        float b0 = bog[d], b1 = bog[d+1];
        #pragma unroll
        for (int h = 0; h < 2; h++) {
            int row = rbase + h*8;
            float2 cv = *(const float2*)&g_cell[(size_t)row*64 + d];
            float2 ov;
            ov.x = sigmoidf_(c[nt][h*2]   + b0) * cv.x;
            ov.y = sigmoidf_(c[nt][h*2+1] + b1) * cv.y;
            *(float2*)&out[(size_t)row*64 + d] = ov;
        }
    }
}

// ================= launch =====================================================
extern "C" void kernel_launch(void* const* d_in, const int* in_sizes, int n_in,
                              void* d_out, int out_size) {
    const float* x      = (const float*)d_in[0];
    const float* Wh     = (const float*)d_in[1];
    const float* bh     = (const float*)d_in[2];
    const float* Wog    = (const float*)d_in[3];
    const float* bog    = (const float*)d_in[4];
    const float* gamma  = (const float*)d_in[5];
    const float* beta   = (const float*)d_in[6];
    const float* initcx = (const float*)d_in[7];
    float* out = (float*)d_out;

    static bool attr_done = false;
    if (!attr_done) {
        cudaFuncSetAttribute(k4_mma,  cudaFuncAttributeMaxDynamicSharedMemorySize, A64_SMEM_BYTES);
        cudaFuncSetAttribute(k7b_mma, cudaFuncAttributeMaxDynamicSharedMemorySize, A128_SMEM_BYTES);
        attr_done = true;
    }

    kprep_w<<<48, 256>>>(Wh, Wog);
    k3_csum_ln<<<BC, 512>>>(x, gamma, beta);
    k4_mma<<<ROWS/64, 512, A64_SMEM_BYTES>>>(x, bh);
    k7a_cell<<<BC, 512>>>(initcx);
    k7b_mma<<<ROWS/128, 512, A128_SMEM_BYTES>>>(x, bog, out);
}

// round 12
// speedup vs baseline: 1.4068x; 1.1810x over previous
#include <cuda_runtime.h>
#include <cuda_bf16.h>
#include <cuda_fp16.h>
#include <cstdint>

// Problem dims
#define BB 4
#define SS 4096
#define HH 8
#define DD 64
#define HD 512
#define TOK (BB*SS)
#define ROWS (TOK*HH)          // 131072 gemm rows
#define CC 32
#define NC (SS/CC)
#define BC (BB*NC)

// ================= scratch ====================================================
__device__ unsigned short g_xh   [ROWS*DD];   // x in fp16 (written by k3)
__device__ unsigned short g_csumh[ROWS*DD];   // normalized csum in fp16
__device__ uint32_t g_fgi[ROWS*DD];           // packed half2(fg, igh)
__device__ float g_cell[ROWS*DD];
__device__ float g_chunksum[BC*HD];
__device__ float g_A [BC*HD];
__device__ float g_Bv[BC*HD];
__device__ int   g_flag1[BC];
__device__ int   g_flag2[BC];
// W pre-packed in mma B-fragment order: [ks][nt][lane][2] u32 (fp16x2 each)
__device__ uint32_t g_WhF[12288];   // GEMM1: 8 ks * 24 nt * 32 * 2
__device__ uint32_t g_WoF[4096];    // GEMM2: 8 ks * 8 nt * 32 * 2

// ================= helpers ====================================================
__device__ __forceinline__ float sigmoidf_(float v) { return 1.f / (1.f + __expf(-v)); }

#define MMA4(c, a0,a1,a2,a3, b0,b1) \
    asm volatile("mma.sync.aligned.m16n8k16.row.col.f32.f16.f16.f32 " \
        "{%0,%1,%2,%3}, {%4,%5,%6,%7}, {%8,%9}, {%0,%1,%2,%3};" \
        : "+f"((c)[0]),"+f"((c)[1]),"+f"((c)[2]),"+f"((c)[3]) \
        : "r"(a0),"r"(a1),"r"(a2),"r"(a3),"r"(b0),"r"(b1))

// ================= prep: W -> B-fragment images + flag reset ==================
__global__ void kprep_w(const float* __restrict__ Wh, const float* __restrict__ Wog) {
    int t = blockIdx.x * blockDim.x + threadIdx.x;
    int stride = gridDim.x * blockDim.x;
    for (int i = t; i < BC; i += stride) { g_flag1[i] = 0; g_flag2[i] = 0; }
    for (int idx = t; idx < 12288; idx += stride) {
        int reg  = idx & 1;
        int lane = (idx >> 1) & 31;
        int nt   = (idx >> 6) % 24;
        int ks   = (idx >> 6) / 24;
        int nquad = nt / 6, ntl = nt % 6;
        int gate = ntl >> 1, dt = ntl & 1;
        int d = nquad*16 + dt*8 + (lane >> 2);
        int n = gate*64 + d;
        int k0 = ks*16 + (lane & 3)*2 + reg*8;
        unsigned short h0 = __half_as_ushort(__float2half_rn(Wh[(size_t)k0*192 + n]));
        unsigned short h1 = __half_as_ushort(__float2half_rn(Wh[(size_t)(k0+1)*192 + n]));
        g_WhF[idx] = (uint32_t)h0 | ((uint32_t)h1 << 16);
    }
    for (int idx = t; idx < 4096; idx += stride) {
        int reg  = idx & 1;
        int lane = (idx >> 1) & 31;
        int nt   = (idx >> 6) % 8;
        int ks   = (idx >> 6) / 8;
        int n = nt*8 + (lane >> 2);
        int k0 = ks*16 + (lane & 3)*2 + reg*8;
        unsigned short h0 = __half_as_ushort(__float2half_rn(Wog[(size_t)k0*64 + n]));
        unsigned short h1 = __half_as_ushort(__float2half_rn(Wog[(size_t)(k0+1)*64 + n]));
        g_WoF[idx] = (uint32_t)h0 | ((uint32_t)h1 << 16);
    }
}

// ================= K3: chunk-sum + lookback + cumsum + LayerNorm ==============
// Also emits fp16 images: g_xh (x) and g_csumh (normalized csum).
__global__ __launch_bounds__(512) void k3_csum_ln(const float* __restrict__ x,
                                                  const float* __restrict__ gamma,
                                                  const float* __restrict__ beta) {
    int bc = blockIdx.x;
    int b = bc / NC, c = bc % NC;
    int tid = threadIdx.x;
    int warp = tid >> 5, lane = tid & 31;
    __shared__ float sm_s[16][33];
    __shared__ float sm_q[16][33];
    __shared__ float sm_mean[32], sm_inv[32];

    size_t base = ((size_t)(b*SS + c*CC))*HD + tid;
    const float* px = x + base;

    // pass 0: own chunk sum, publish
    float sown = 0.f;
    #pragma unroll
    for (int i = 0; i < CC; i++) sown += px[(size_t)i*HD];
    g_chunksum[(size_t)bc*HD + tid] = sown;
    __threadfence();
    __syncthreads();
    if (tid == 0) atomicExch(&g_flag1[bc], 1);

    // lookback
    if (tid < c) {
        while (atomicAdd(&g_flag1[b*NC + tid], 0) == 0) __nanosleep(64);
        __threadfence();
    }
    __syncthreads();

    float run = 0.f;
    {
        const float* pcs = g_chunksum + (size_t)b*NC*HD + tid;
        int j = 0;
        for (; j + 4 <= c; j += 4)
            run += pcs[(size_t)(j+0)*HD] + pcs[(size_t)(j+1)*HD]
                 + pcs[(size_t)(j+2)*HD] + pcs[(size_t)(j+3)*HD];
        for (; j < c; j++) run += pcs[(size_t)j*HD];
    }

    float ga = gamma[tid], be = beta[tid];
    unsigned short* pch = g_csumh + base;
    unsigned short* pxh = g_xh + base;

    // phase 1: per-token per-warp partial (sum, sumsq)
    float r1 = run;
    #pragma unroll
    for (int i = 0; i < CC; i++) {
        float val = r1;
        r1 += px[(size_t)i*HD];
        float s = val, q = val*val;
        #pragma unroll
        for (int o = 16; o; o >>= 1) {
            s += __shfl_xor_sync(0xffffffffu, s, o);
            q += __shfl_xor_sync(0xffffffffu, q, o);
        }
        if (lane == 0) { sm_s[warp][i] = s; sm_q[warp][i] = q; }
    }
    __syncthreads();

    // phase 2: reduce 16 warp-partials per token
    {
        int t = tid >> 4, k = tid & 15;
        float s = sm_s[k][t], q = sm_q[k][t];
        #pragma unroll
        for (int o = 8; o; o >>= 1) {
            s += __shfl_xor_sync(0xffffffffu, s, o);
            q += __shfl_xor_sync(0xffffffffu, q, o);
        }
        if (k == 0) {
            float m = s * (1.f/512.f);
            float v = q * (1.f/512.f) - m*m;
            sm_mean[t] = m;
            sm_inv[t]  = rsqrtf(v + 1e-5f);
        }
    }
    __syncthreads();

    // phase 3: rewalk; write fp16 csum + fp16 x
    float r2 = run;
    #pragma unroll
    for (int i = 0; i < CC; i++) {
        float val = r2;
        float xv = px[(size_t)i*HD];
        r2 += xv;
        float cs = (val - sm_mean[i]) * sm_inv[i] * ga + be;
        pch[(size_t)i*HD] = __half_as_ushort(__float2half_rn(cs));
        pxh[(size_t)i*HD] = __half_as_ushort(__float2half_rn(xv));
    }
}

// ================= K7a: chunk state + lookback + replay cell ==================
__global__ __launch_bounds__(512) void k7a_cell(const float* __restrict__ initcx) {
    int bc = blockIdx.x;
    int b = bc / NC, c = bc % NC;
    int tid = threadIdx.x;

    size_t base = ((size_t)(b*SS + c*CC))*HD + tid;
    const uint32_t* pfi = g_fgi + base;

    // pass 0: own chunk affine state (a, bv), publish
    float a = 1.f, bv = 0.f;
    #pragma unroll
    for (int i = 0; i < CC; i++) {
        float2 fg = __half22float2(*(const __half2*)&pfi[(size_t)i*HD]);
        a *= fg.x;
        bv = bv * fg.x + fg.y;
    }
    g_A [(size_t)bc*HD + tid] = a;
    g_Bv[(size_t)bc*HD + tid] = bv;
    __threadfence();
    __syncthreads();
    if (tid == 0) atomicExch(&g_flag2[bc], 1);

    // lookback
    if (tid < c) {
        while (atomicAdd(&g_flag2[b*NC + tid], 0) == 0) __nanosleep(64);
        __threadfence();
    }
    __syncthreads();

    // batched fold
    float carry = initcx[tid];
    {
        const float* pA = g_A  + (size_t)b*NC*HD + tid;
        const float* pB = g_Bv + (size_t)b*NC*HD + tid;
        int j = 0;
        for (; j + 8 <= c; j += 8) {
            float av[8], bw[8];
            #pragma unroll
            for (int u = 0; u < 8; u++) {
                av[u] = pA[(size_t)(j+u)*HD];
                bw[u] = pB[(size_t)(j+u)*HD];
            }
            #pragma unroll
            for (int u = 0; u < 8; u++)
                carry = av[u] * carry + bw[u];
        }
        for (; j < c; j++)
            carry = pA[(size_t)j*HD] * carry + pB[(size_t)j*HD];
    }

    // replay
    float* pcell = g_cell + base;
    float cell = carry;
    #pragma unroll
    for (int i = 0; i < CC; i++) {
        float2 fg = __half22float2(*(const __half2*)&pfi[(size_t)i*HD]);
        cell = fg.x * cell + fg.y;
        pcell[(size_t)i*HD] = cell;
    }
}

// ================= A tile converts into SMEM ==================================
#define APITCH 136
#define A64_SMEM_BYTES (64*APITCH*2)      // 17408
#define A128_SMEM_BYTES (128*APITCH*2)    // 34816

// 64-row tile, 512 threads: r = tid>>3, q = tid&7 (16 halves each).
// Sources already fp16: pure copy.
__device__ __forceinline__ void convert_A64(unsigned short* Ah, int row0, int tid) {
    int r = tid >> 3;
    int q = tid & 7;
    const unsigned short* src = (q < 4)
        ? (g_xh    + (size_t)(row0 + r)*64 + q*16)
        : (g_csumh + (size_t)(row0 + r)*64 + (q-4)*16);
    int kbase = q*16;
    uint4 v0 = *(const uint4*)src;
    uint4 v1 = *(const uint4*)(src + 8);
    *(uint4*)&Ah[r*APITCH + kbase]     = v0;
    *(uint4*)&Ah[r*APITCH + kbase + 8] = v1;
}

// 128-row tile, 512 threads: r = tid>>2, q = tid&3 (32 k each).
// q<2: copy xh halves; q>=2: convert cell f32 -> fp16.
__device__ __forceinline__ void convert_A128(unsigned short* Ah, int row0, int tid) {
    int r = tid >> 2;
    int q = tid & 3;
    if (q < 2) {
        const unsigned short* src = g_xh + (size_t)(row0 + r)*64 + q*32;
        int kbase = q*32;
        #pragma unroll
        for (int i = 0; i < 4; i++)
            *(uint4*)&Ah[r*APITCH + kbase + i*8] = *(const uint4*)(src + i*8);
    } else {
        const float* src = g_cell + (size_t)(row0 + r)*64 + (q-2)*32;
        int kbase = 64 + (q-2)*32;
        const float4* p4 = (const float4*)src;
        #pragma unroll
        for (int i = 0; i < 8; i++) {
            float4 v = p4[i];
            unsigned short h0 = __half_as_ushort(__float2half_rn(v.x));
            unsigned short h1 = __half_as_ushort(__float2half_rn(v.y));
            unsigned short h2 = __half_as_ushort(__float2half_rn(v.z));
            unsigned short h3 = __half_as_ushort(__float2half_rn(v.w));
            int k = kbase + i*4;
            *(uint32_t*)&Ah[r*APITCH + k]     = (uint32_t)h0 | ((uint32_t)h1 << 16);
            *(uint32_t*)&Ah[r*APITCH + k + 2] = (uint32_t)h2 | ((uint32_t)h3 << 16);
        }
    }
}

// ================= K4: GEMM1 via mma.sync + fused gates =======================
// Block: 512 thr (16 warps), M-tile 64. Warp = slab(4)*16 rows x nquad(4)*48 cols.
__global__ __launch_bounds__(512, 2) void k4_mma(const float* __restrict__ bhid) {
    extern __shared__ unsigned short smu[];
    unsigned short* Ah = smu;
    int tid = threadIdx.x, lane = tid & 31, wid = tid >> 5;
    int row0 = blockIdx.x * 64;

    convert_A64(Ah, row0, tid);
    __syncthreads();

    int slab = wid >> 2, nquad = wid & 3;
    int m0 = slab*16 + (lane >> 2);
    int kq = (lane & 3)*2;

    float c[6][4];
    #pragma unroll
    for (int j = 0; j < 6; j++)
        #pragma unroll
        for (int e = 0; e < 4; e++) c[j][e] = 0.f;

    #pragma unroll
    for (int ks = 0; ks < 8; ks++) {
        int ka = ks*16 + kq;
        uint32_t a0 = *(const uint32_t*)&Ah[m0*APITCH + ka];
        uint32_t a1 = *(const uint32_t*)&Ah[(m0+8)*APITCH + ka];
        uint32_t a2 = *(const uint32_t*)&Ah[m0*APITCH + ka + 8];
        uint32_t a3 = *(const uint32_t*)&Ah[(m0+8)*APITCH + ka + 8];
        const uint32_t* bb = g_WhF + ((size_t)(ks*24 + nquad*6)*32 + lane)*2;
        #pragma unroll
        for (int nt = 0; nt < 6; nt++) {
            uint2 b2 = *(const uint2*)(bb + nt*64);
            MMA4(c[nt], a0, a1, a2, a3, b2.x, b2.y);
        }
    }

    // epilogue: gate triple for d at c[dt], c[dt+2], c[dt+4]; pack half2(fg, igh)
    int u0 = (lane & 3)*2;
    int rbase = row0 + slab*16 + (lane >> 2);
    #pragma unroll
    for (int dt = 0; dt < 2; dt++) {
        int d = nquad*16 + dt*8 + u0;
        float bi0 = bhid[d],       bi1 = bhid[d+1];
        float bf0 = bhid[64 + d],  bf1 = bhid[64 + d + 1];
        float bq0 = bhid[128 + d], bq1 = bhid[128 + d + 1];
        #pragma unroll
        for (int h = 0; h < 2; h++) {
            int row = rbase + h*8;
            float i0 = c[dt][h*2]   + bi0, i1 = c[dt][h*2+1]   + bi1;
            float f0 = c[dt+2][h*2] + bf0, f1 = c[dt+2][h*2+1] + bf1;
            float q0 = c[dt+4][h*2] + bq0, q1 = c[dt+4][h*2+1] + bq1;
            float fg0 = sigmoidf_(f0), fg1 = sigmoidf_(f1);
            float ig0 = sigmoidf_(i0) * fmaxf(q0, 0.f);
            float ig1 = sigmoidf_(i1) * fmaxf(q1, 0.f);
            uint2 pk;
            __half2 p0 = __floats2half2_rn(fg0, ig0);
            __half2 p1 = __floats2half2_rn(fg1, ig1);
            pk.x = *(uint32_t*)&p0;
            pk.y = *(uint32_t*)&p1;
            *(uint2*)&g_fgi[(size_t)row*64 + d] = pk;
        }
    }
}

// ================= K7b: GEMM2 via mma.sync + fused output gate ================
// Block: 512 thr (16 warps), M-tile 128. Warp = slab(8)*16 rows x nhalf(2)*32 cols.
__global__ __launch_bounds__(512, 2) void k7b_mma(const float* __restrict__ bog,
                                                  float* __restrict__ out) {
    extern __shared__ unsigned short smu[];
    unsigned short* Ah = smu;
    int tid = threadIdx.x, lane = tid & 31, wid = tid >> 5;
    int row0 = blockIdx.x * 128;

    convert_A128(Ah, row0, tid);
    __syncthreads();

    int slab = wid >> 1, nhalf = wid & 1;
    int m0 = slab*16 + (lane >> 2);
    int kq = (lane & 3)*2;

    float c[4][4];
    #pragma unroll
    for (int j = 0; j < 4; j++)
        #pragma unroll
        for (int e = 0; e < 4; e++) c[j][e] = 0.f;

    #pragma unroll
    for (int ks = 0; ks < 8; ks++) {
        int ka = ks*16 + kq;
        uint32_t a0 = *(const uint32_t*)&Ah[m0*APITCH + ka];
        uint32_t a1 = *(const uint32_t*)&Ah[(m0+8)*APITCH + ka];
        uint32_t a2 = *(const uint32_t*)&Ah[m0*APITCH + ka + 8];
        uint32_t a3 = *(const uint32_t*)&Ah[(m0+8)*APITCH + ka + 8];
        const uint32_t* bb = g_WoF + ((size_t)(ks*8 + nhalf*4)*32 + lane)*2;
        #pragma unroll
        for (int nt = 0; nt < 4; nt++) {
            uint2 b2 = *(const uint2*)(bb + nt*64);
            MMA4(c[nt], a0, a1, a2, a3, b2.x, b2.y);
        }
    }

    int u0 = (lane & 3)*2;
    int rbase = row0 + slab*16 + (lane >> 2);
    #pragma unroll
    for (int nt = 0; nt < 4; nt++) {
        int d = (nhalf*4 + nt)*8 + u0;
        float b0 = bog[d], b1 = bog[d+1];
        #pragma unroll
        for (int h = 0; h < 2; h++) {
            int row = rbase + h*8;
            float2 cv = *(const float2*)&g_cell[(size_t)row*64 + d];
            float2 ov;
            ov.x = sigmoidf_(c[nt][h*2]   + b0) * cv.x;
            ov.y = sigmoidf_(c[nt][h*2+1] + b1) * cv.y;
            *(float2*)&out[(size_t)row*64 + d] = ov;
        }
    }
}

// ================= launch =====================================================
extern "C" void kernel_launch(void* const* d_in, const int* in_sizes, int n_in,
                              void* d_out, int out_size) {
    const float* x      = (const float*)d_in[0];
    const float* Wh     = (const float*)d_in[1];
    const float* bh     = (const float*)d_in[2];
    const float* Wog    = (const float*)d_in[3];
    const float* bog    = (const float*)d_in[4];
    const float* gamma  = (const float*)d_in[5];
    const float* beta   = (const float*)d_in[6];
    const float* initcx = (const float*)d_in[7];
    float* out = (float*)d_out;

    static bool attr_done = false;
    if (!attr_done) {
        cudaFuncSetAttribute(k4_mma,  cudaFuncAttributeMaxDynamicSharedMemorySize, A64_SMEM_BYTES);
        cudaFuncSetAttribute(k7b_mma, cudaFuncAttributeMaxDynamicSharedMemorySize, A128_SMEM_BYTES);
        attr_done = true;
    }

    kprep_w<<<48, 256>>>(Wh, Wog);
    k3_csum_ln<<<BC, 512>>>(x, gamma, beta);
    k4_mma<<<ROWS/64, 512, A64_SMEM_BYTES>>>(bh);
    k7a_cell<<<BC, 512>>>(initcx);
    k7b_mma<<<ROWS/128, 512, A128_SMEM_BYTES>>>(bog, out);
}

// round 13
// speedup vs baseline: 1.5108x; 1.0739x over previous
#include <cuda_runtime.h>
#include <cuda_bf16.h>
#include <cuda_fp16.h>
#include <cstdint>

// Problem dims
#define BB 4
#define SS 4096
#define HH 8
#define DD 64
#define HD 512
#define TOK (BB*SS)
#define ROWS (TOK*HH)          // 131072 gemm rows
#define CC 32
#define NC (SS/CC)
#define BC (BB*NC)

// ================= scratch ====================================================
__device__ unsigned short g_xh   [ROWS*DD];   // x in fp16 (written by k3)
__device__ unsigned short g_csumh[ROWS*DD];   // normalized csum in fp16
__device__ uint32_t g_fgi[ROWS*DD];           // packed half2(fg, igh)
__device__ unsigned short g_cellh[ROWS*DD];   // cell in fp16
__device__ float g_chunksum[BC*HD];
__device__ float2 g_AB[BC*HD];                // packed (A, Bv)
__device__ int   g_flag1[BC];
__device__ int   g_flag2[BC];
// W pre-packed in mma B-fragment order: [ks][nt][lane][2] u32 (fp16x2 each)
__device__ uint32_t g_WhF[12288];   // GEMM1: 8 ks * 24 nt * 32 * 2
__device__ uint32_t g_WoF[4096];    // GEMM2: 8 ks * 8 nt * 32 * 2

// ================= helpers ====================================================
__device__ __forceinline__ float sigmoidf_(float v) { return 1.f / (1.f + __expf(-v)); }

#define MMA4(c, a0,a1,a2,a3, b0,b1) \
    asm volatile("mma.sync.aligned.m16n8k16.row.col.f32.f16.f16.f32 " \
        "{%0,%1,%2,%3}, {%4,%5,%6,%7}, {%8,%9}, {%0,%1,%2,%3};" \
        : "+f"((c)[0]),"+f"((c)[1]),"+f"((c)[2]),"+f"((c)[3]) \
        : "r"(a0),"r"(a1),"r"(a2),"r"(a3),"r"(b0),"r"(b1))

// ================= prep: W -> B-fragment images + flag reset ==================
__global__ void kprep_w(const float* __restrict__ Wh, const float* __restrict__ Wog) {
    int t = blockIdx.x * blockDim.x + threadIdx.x;
    int stride = gridDim.x * blockDim.x;
    for (int i = t; i < BC; i += stride) { g_flag1[i] = 0; g_flag2[i] = 0; }
    for (int idx = t; idx < 12288; idx += stride) {
        int reg  = idx & 1;
        int lane = (idx >> 1) & 31;
        int nt   = (idx >> 6) % 24;
        int ks   = (idx >> 6) / 24;
        int nquad = nt / 6, ntl = nt % 6;
        int gate = ntl >> 1, dt = ntl & 1;
        int d = nquad*16 + dt*8 + (lane >> 2);
        int n = gate*64 + d;
        int k0 = ks*16 + (lane & 3)*2 + reg*8;
        unsigned short h0 = __half_as_ushort(__float2half_rn(Wh[(size_t)k0*192 + n]));
        unsigned short h1 = __half_as_ushort(__float2half_rn(Wh[(size_t)(k0+1)*192 + n]));
        g_WhF[idx] = (uint32_t)h0 | ((uint32_t)h1 << 16);
    }
    for (int idx = t; idx < 4096; idx += stride) {
        int reg  = idx & 1;
        int lane = (idx >> 1) & 31;
        int nt   = (idx >> 6) % 8;
        int ks   = (idx >> 6) / 8;
        int n = nt*8 + (lane >> 2);
        int k0 = ks*16 + (lane & 3)*2 + reg*8;
        unsigned short h0 = __half_as_ushort(__float2half_rn(Wog[(size_t)k0*64 + n]));
        unsigned short h1 = __half_as_ushort(__float2half_rn(Wog[(size_t)(k0+1)*64 + n]));
        g_WoF[idx] = (uint32_t)h0 | ((uint32_t)h1 << 16);
    }
}

// ================= K3: chunk-sum + lookback + cumsum + LayerNorm ==============
// x slice cached in registers (read once); emits fp16 csum + fp16 x images.
__global__ __launch_bounds__(512) void k3_csum_ln(const float* __restrict__ x,
                                                  const float* __restrict__ gamma,
                                                  const float* __restrict__ beta) {
    int bc = blockIdx.x;
    int b = bc / NC, c = bc % NC;
    int tid = threadIdx.x;
    int warp = tid >> 5, lane = tid & 31;
    __shared__ float sm_s[16][33];
    __shared__ float sm_q[16][33];
    __shared__ float sm_mean[32], sm_inv[32];

    size_t base = ((size_t)(b*SS + c*CC))*HD + tid;
    const float* px = x + base;

    // pass 0: read x slice into registers; own chunk sum; publish
    float xr[CC];
    float sown = 0.f;
    #pragma unroll
    for (int i = 0; i < CC; i++) { xr[i] = px[(size_t)i*HD]; sown += xr[i]; }
    g_chunksum[(size_t)bc*HD + tid] = sown;
    __threadfence();
    __syncthreads();
    if (tid == 0) atomicExch(&g_flag1[bc], 1);

    // lookback
    if (tid < c) {
        while (atomicAdd(&g_flag1[b*NC + tid], 0) == 0) __nanosleep(64);
        __threadfence();
    }
    __syncthreads();

    float run = 0.f;
    {
        const float* pcs = g_chunksum + (size_t)b*NC*HD + tid;
        int j = 0;
        for (; j + 4 <= c; j += 4)
            run += pcs[(size_t)(j+0)*HD] + pcs[(size_t)(j+1)*HD]
                 + pcs[(size_t)(j+2)*HD] + pcs[(size_t)(j+3)*HD];
        for (; j < c; j++) run += pcs[(size_t)j*HD];
    }

    float ga = gamma[tid], be = beta[tid];
    unsigned short* pch = g_csumh + base;
    unsigned short* pxh = g_xh + base;

    // phase 1: per-token per-warp partial (sum, sumsq)
    float r1 = run;
    #pragma unroll
    for (int i = 0; i < CC; i++) {
        float val = r1;
        r1 += xr[i];
        float s = val, q = val*val;
        #pragma unroll
        for (int o = 16; o; o >>= 1) {
            s += __shfl_xor_sync(0xffffffffu, s, o);
            q += __shfl_xor_sync(0xffffffffu, q, o);
        }
        if (lane == 0) { sm_s[warp][i] = s; sm_q[warp][i] = q; }
    }
    __syncthreads();

    // phase 2: reduce 16 warp-partials per token
    {
        int t = tid >> 4, k = tid & 15;
        float s = sm_s[k][t], q = sm_q[k][t];
        #pragma unroll
        for (int o = 8; o; o >>= 1) {
            s += __shfl_xor_sync(0xffffffffu, s, o);
            q += __shfl_xor_sync(0xffffffffu, q, o);
        }
        if (k == 0) {
            float m = s * (1.f/512.f);
            float v = q * (1.f/512.f) - m*m;
            sm_mean[t] = m;
            sm_inv[t]  = rsqrtf(v + 1e-5f);
        }
    }
    __syncthreads();

    // phase 3: rewalk from registers; write fp16 csum + fp16 x
    float r2 = run;
    #pragma unroll
    for (int i = 0; i < CC; i++) {
        float val = r2;
        r2 += xr[i];
        float cs = (val - sm_mean[i]) * sm_inv[i] * ga + be;
        pch[(size_t)i*HD] = __half_as_ushort(__float2half_rn(cs));
        pxh[(size_t)i*HD] = __half_as_ushort(__float2half_rn(xr[i]));
    }
}

// ================= K7a: chunk state + lookback + replay cell ==================
__global__ __launch_bounds__(512) void k7a_cell(const float* __restrict__ initcx) {
    int bc = blockIdx.x;
    int b = bc / NC, c = bc % NC;
    int tid = threadIdx.x;

    size_t base = ((size_t)(b*SS + c*CC))*HD + tid;
    const uint32_t* pfi = g_fgi + base;

    // pass 0: own chunk affine state (a, bv), publish packed
    float a = 1.f, bv = 0.f;
    #pragma unroll
    for (int i = 0; i < CC; i++) {
        float2 fg = __half22float2(*(const __half2*)&pfi[(size_t)i*HD]);
        a *= fg.x;
        bv = bv * fg.x + fg.y;
    }
    g_AB[(size_t)bc*HD + tid] = make_float2(a, bv);
    __threadfence();
    __syncthreads();
    if (tid == 0) atomicExch(&g_flag2[bc], 1);

    // lookback
    if (tid < c) {
        while (atomicAdd(&g_flag2[b*NC + tid], 0) == 0) __nanosleep(64);
        __threadfence();
    }
    __syncthreads();

    // batched fold (8-wide register prefetch)
    float carry = initcx[tid];
    {
        const float2* pAB = g_AB + (size_t)b*NC*HD + tid;
        int j = 0;
        for (; j + 8 <= c; j += 8) {
            float2 ab[8];
            #pragma unroll
            for (int u = 0; u < 8; u++) ab[u] = pAB[(size_t)(j+u)*HD];
            #pragma unroll
            for (int u = 0; u < 8; u++)
                carry = ab[u].x * carry + ab[u].y;
        }
        for (; j < c; j++) {
            float2 ab = pAB[(size_t)j*HD];
            carry = ab.x * carry + ab.y;
        }
    }

    // replay; write fp16 cell
    unsigned short* pcell = g_cellh + base;
    float cell = carry;
    #pragma unroll
    for (int i = 0; i < CC; i++) {
        float2 fg = __half22float2(*(const __half2*)&pfi[(size_t)i*HD]);
        cell = fg.x * cell + fg.y;
        pcell[(size_t)i*HD] = __half_as_ushort(__float2half_rn(cell));
    }
}

// ================= A tile converts into SMEM ==================================
#define APITCH 136
#define A64_SMEM_BYTES (64*APITCH*2)      // 17408
#define A128_SMEM_BYTES (128*APITCH*2)    // 34816

// 64-row tile, 512 threads: r = tid>>3, q = tid&7 (16 halves each). Pure copy.
__device__ __forceinline__ void convert_A64(unsigned short* Ah, int row0, int tid) {
    int r = tid >> 3;
    int q = tid & 7;
    const unsigned short* src = (q < 4)
        ? (g_xh    + (size_t)(row0 + r)*64 + q*16)
        : (g_csumh + (size_t)(row0 + r)*64 + (q-4)*16);
    int kbase = q*16;
    uint4 v0 = *(const uint4*)src;
    uint4 v1 = *(const uint4*)(src + 8);
    *(uint4*)&Ah[r*APITCH + kbase]     = v0;
    *(uint4*)&Ah[r*APITCH + kbase + 8] = v1;
}

// 128-row tile, 512 threads: r = tid>>2, q = tid&3 (32 halves each). Pure copy.
__device__ __forceinline__ void convert_A128(unsigned short* Ah, int row0, int tid) {
    int r = tid >> 2;
    int q = tid & 3;
    const unsigned short* src = (q < 2)
        ? (g_xh    + (size_t)(row0 + r)*64 + q*32)
        : (g_cellh + (size_t)(row0 + r)*64 + (q-2)*32);
    int kbase = q*32;
    #pragma unroll
    for (int i = 0; i < 4; i++)
        *(uint4*)&Ah[r*APITCH + kbase + i*8] = *(const uint4*)(src + i*8);
}

// ================= K4: GEMM1 via mma.sync + fused gates =======================
// Block: 512 thr (16 warps), M-tile 64. Warp = slab(4)*16 rows x nquad(4)*48 cols.
__global__ __launch_bounds__(512, 2) void k4_mma(const float* __restrict__ bhid) {
    extern __shared__ unsigned short smu[];
    unsigned short* Ah = smu;
    int tid = threadIdx.x, lane = tid & 31, wid = tid >> 5;
    int row0 = blockIdx.x * 64;

    convert_A64(Ah, row0, tid);
    __syncthreads();

    int slab = wid >> 2, nquad = wid & 3;
    int m0 = slab*16 + (lane >> 2);
    int kq = (lane & 3)*2;

    float c[6][4];
    #pragma unroll
    for (int j = 0; j < 6; j++)
        #pragma unroll
        for (int e = 0; e < 4; e++) c[j][e] = 0.f;

    #pragma unroll
    for (int ks = 0; ks < 8; ks++) {
        int ka = ks*16 + kq;
        uint32_t a0 = *(const uint32_t*)&Ah[m0*APITCH + ka];
        uint32_t a1 = *(const uint32_t*)&Ah[(m0+8)*APITCH + ka];
        uint32_t a2 = *(const uint32_t*)&Ah[m0*APITCH + ka + 8];
        uint32_t a3 = *(const uint32_t*)&Ah[(m0+8)*APITCH + ka + 8];
        const uint32_t* bb = g_WhF + ((size_t)(ks*24 + nquad*6)*32 + lane)*2;
        #pragma unroll
        for (int nt = 0; nt < 6; nt++) {
            uint2 b2 = *(const uint2*)(bb + nt*64);
            MMA4(c[nt], a0, a1, a2, a3, b2.x, b2.y);
        }
    }

    // epilogue: gate triple for d at c[dt], c[dt+2], c[dt+4]; pack half2(fg, igh)
    int u0 = (lane & 3)*2;
    int rbase = row0 + slab*16 + (lane >> 2);
    #pragma unroll
    for (int dt = 0; dt < 2; dt++) {
        int d = nquad*16 + dt*8 + u0;
        float bi0 = bhid[d],       bi1 = bhid[d+1];
        float bf0 = bhid[64 + d],  bf1 = bhid[64 + d + 1];
        float bq0 = bhid[128 + d], bq1 = bhid[128 + d + 1];
        #pragma unroll
        for (int h = 0; h < 2; h++) {
            int row = rbase + h*8;
            float i0 = c[dt][h*2]   + bi0, i1 = c[dt][h*2+1]   + bi1;
            float f0 = c[dt+2][h*2] + bf0, f1 = c[dt+2][h*2+1] + bf1;
            float q0 = c[dt+4][h*2] + bq0, q1 = c[dt+4][h*2+1] + bq1;
            float fg0 = sigmoidf_(f0), fg1 = sigmoidf_(f1);
            float ig0 = sigmoidf_(i0) * fmaxf(q0, 0.f);
            float ig1 = sigmoidf_(i1) * fmaxf(q1, 0.f);
            uint2 pk;
            __half2 p0 = __floats2half2_rn(fg0, ig0);
            __half2 p1 = __floats2half2_rn(fg1, ig1);
            pk.x = *(uint32_t*)&p0;
            pk.y = *(uint32_t*)&p1;
            *(uint2*)&g_fgi[(size_t)row*64 + d] = pk;
        }
    }
}

// ================= K7b: GEMM2 via mma.sync + fused output gate ================
// Block: 512 thr (16 warps), M-tile 128. Warp = slab(8)*16 rows x nhalf(2)*32 cols.
__global__ __launch_bounds__(512, 2) void k7b_mma(const float* __restrict__ bog,
                                                  float* __restrict__ out) {
    extern __shared__ unsigned short smu[];
    unsigned short* Ah = smu;
    int tid = threadIdx.x, lane = tid & 31, wid = tid >> 5;
    int row0 = blockIdx.x * 128;

    convert_A128(Ah, row0, tid);
    __syncthreads();

    int slab = wid >> 1, nhalf = wid & 1;
    int m0 = slab*16 + (lane >> 2);
    int kq = (lane & 3)*2;

    float c[4][4];
    #pragma unroll
    for (int j = 0; j < 4; j++)
        #pragma unroll
        for (int e = 0; e < 4; e++) c[j][e] = 0.f;

    #pragma unroll
    for (int ks = 0; ks < 8; ks++) {
        int ka = ks*16 + kq;
        uint32_t a0 = *(const uint32_t*)&Ah[m0*APITCH + ka];
        uint32_t a1 = *(const uint32_t*)&Ah[(m0+8)*APITCH + ka];
        uint32_t a2 = *(const uint32_t*)&Ah[m0*APITCH + ka + 8];
        uint32_t a3 = *(const uint32_t*)&Ah[(m0+8)*APITCH + ka + 8];
        const uint32_t* bb = g_WoF + ((size_t)(ks*8 + nhalf*4)*32 + lane)*2;
        #pragma unroll
        for (int nt = 0; nt < 4; nt++) {
            uint2 b2 = *(const uint2*)(bb + nt*64);
            MMA4(c[nt], a0, a1, a2, a3, b2.x, b2.y);
        }
    }

    int u0 = (lane & 3)*2;
    int rbase = row0 + slab*16 + (lane >> 2);
    #pragma unroll
    for (int nt = 0; nt < 4; nt++) {
        int d = (nhalf*4 + nt)*8 + u0;
        float b0 = bog[d], b1 = bog[d+1];
        #pragma unroll
        for (int h = 0; h < 2; h++) {
            int row = rbase + h*8;
            float2 cv = __half22float2(*(const __half2*)&g_cellh[(size_t)row*64 + d]);
            float2 ov;
            ov.x = sigmoidf_(c[nt][h*2]   + b0) * cv.x;
            ov.y = sigmoidf_(c[nt][h*2+1] + b1) * cv.y;
            *(float2*)&out[(size_t)row*64 + d] = ov;
        }
    }
}

// ================= launch =====================================================
extern "C" void kernel_launch(void* const* d_in, const int* in_sizes, int n_in,
                              void* d_out, int out_size) {
    const float* x      = (const float*)d_in[0];
    const float* Wh     = (const float*)d_in[1];
    const float* bh     = (const float*)d_in[2];
    const float* Wog    = (const float*)d_in[3];
    const float* bog    = (const float*)d_in[4];
    const float* gamma  = (const float*)d_in[5];
    const float* beta   = (const float*)d_in[6];
    const float* initcx = (const float*)d_in[7];
    float* out = (float*)d_out;

    static bool attr_done = false;
    if (!attr_done) {
        cudaFuncSetAttribute(k4_mma,  cudaFuncAttributeMaxDynamicSharedMemorySize, A64_SMEM_BYTES);
        cudaFuncSetAttribute(k7b_mma, cudaFuncAttributeMaxDynamicSharedMemorySize, A128_SMEM_BYTES);
        attr_done = true;
    }

    kprep_w<<<48, 256>>>(Wh, Wog);
    k3_csum_ln<<<BC, 512>>>(x, gamma, beta);
    k4_mma<<<ROWS/64, 512, A64_SMEM_BYTES>>>(bh);
    k7a_cell<<<BC, 512>>>(initcx);
    k7b_mma<<<ROWS/128, 512, A128_SMEM_BYTES>>>(bog, out);
}

// round 14
// speedup vs baseline: 1.5436x; 1.0218x over previous
#include <cuda_runtime.h>
#include <cuda_bf16.h>
#include <cuda_fp16.h>
#include <cstdint>

// Problem dims
#define BB 4
#define SS 4096
#define HH 8
#define DD 64
#define HD 512
#define TOK (BB*SS)
#define ROWS (TOK*HH)          // 131072 gemm rows
#define CC 32
#define NC (SS/CC)
#define BC (BB*NC)

// ================= scratch ====================================================
__device__ unsigned short g_xh   [ROWS*DD];   // x in fp16 (written by k3)
__device__ unsigned short g_csumh[ROWS*DD];   // normalized csum in fp16
__device__ uint32_t g_fgi[ROWS*DD];           // packed half2(fg, igh)
__device__ float g_chunksum[BC*HD];
__device__ float2 g_AB[BC*HD];                // packed (A, Bv)
__device__ int   g_flag1[BC];
__device__ int   g_flag2[BC];
// W pre-packed in mma B-fragment order: [ks][nt][lane][2] u32 (fp16x2 each)
__device__ uint32_t g_WhF[12288];   // GEMM1: 8 ks * 24 nt * 32 * 2
__device__ uint32_t g_WoF[4096];    // GEMM2: 8 ks * 8 nt * 32 * 2

// ================= helpers ====================================================
__device__ __forceinline__ float sigmoidf_(float v) { return 1.f / (1.f + __expf(-v)); }

#define MMA4(c, a0,a1,a2,a3, b0,b1) \
    asm volatile("mma.sync.aligned.m16n8k16.row.col.f32.f16.f16.f32 " \
        "{%0,%1,%2,%3}, {%4,%5,%6,%7}, {%8,%9}, {%0,%1,%2,%3};" \
        : "+f"((c)[0]),"+f"((c)[1]),"+f"((c)[2]),"+f"((c)[3]) \
        : "r"(a0),"r"(a1),"r"(a2),"r"(a3),"r"(b0),"r"(b1))

// ================= prep: W -> B-fragment images + flag reset ==================
__global__ void kprep_w(const float* __restrict__ Wh, const float* __restrict__ Wog) {
    int t = blockIdx.x * blockDim.x + threadIdx.x;
    int stride = gridDim.x * blockDim.x;
    for (int i = t; i < BC; i += stride) { g_flag1[i] = 0; g_flag2[i] = 0; }
    for (int idx = t; idx < 12288; idx += stride) {
        int reg  = idx & 1;
        int lane = (idx >> 1) & 31;
        int nt   = (idx >> 6) % 24;
        int ks   = (idx >> 6) / 24;
        int nquad = nt / 6, ntl = nt % 6;
        int gate = ntl >> 1, dt = ntl & 1;
        int d = nquad*16 + dt*8 + (lane >> 2);
        int n = gate*64 + d;
        int k0 = ks*16 + (lane & 3)*2 + reg*8;
        unsigned short h0 = __half_as_ushort(__float2half_rn(Wh[(size_t)k0*192 + n]));
        unsigned short h1 = __half_as_ushort(__float2half_rn(Wh[(size_t)(k0+1)*192 + n]));
        g_WhF[idx] = (uint32_t)h0 | ((uint32_t)h1 << 16);
    }
    for (int idx = t; idx < 4096; idx += stride) {
        int reg  = idx & 1;
        int lane = (idx >> 1) & 31;
        int nt   = (idx >> 6) % 8;
        int ks   = (idx >> 6) / 8;
        int n = nt*8 + (lane >> 2);
        int k0 = ks*16 + (lane & 3)*2 + reg*8;
        unsigned short h0 = __half_as_ushort(__float2half_rn(Wog[(size_t)k0*64 + n]));
        unsigned short h1 = __half_as_ushort(__float2half_rn(Wog[(size_t)(k0+1)*64 + n]));
        g_WoF[idx] = (uint32_t)h0 | ((uint32_t)h1 << 16);
    }
}

// ================= K3: chunk-sum + lookback + cumsum + LayerNorm ==============
__global__ __launch_bounds__(512) void k3_csum_ln(const float* __restrict__ x,
                                                  const float* __restrict__ gamma,
                                                  const float* __restrict__ beta) {
    int bc = blockIdx.x;
    int b = bc / NC, c = bc % NC;
    int tid = threadIdx.x;
    int warp = tid >> 5, lane = tid & 31;
    __shared__ float sm_s[16][33];
    __shared__ float sm_q[16][33];
    __shared__ float sm_mean[32], sm_inv[32];

    size_t base = ((size_t)(b*SS + c*CC))*HD + tid;
    const float* px = x + base;

    // pass 0: read x slice into registers; own chunk sum; publish
    float xr[CC];
    float sown = 0.f;
    #pragma unroll
    for (int i = 0; i < CC; i++) { xr[i] = px[(size_t)i*HD]; sown += xr[i]; }
    g_chunksum[(size_t)bc*HD + tid] = sown;
    __threadfence();
    __syncthreads();
    if (tid == 0) atomicExch(&g_flag1[bc], 1);

    // lookback
    if (tid < c) {
        while (atomicAdd(&g_flag1[b*NC + tid], 0) == 0) __nanosleep(64);
        __threadfence();
    }
    __syncthreads();

    float run = 0.f;
    {
        const float* pcs = g_chunksum + (size_t)b*NC*HD + tid;
        int j = 0;
        for (; j + 4 <= c; j += 4)
            run += pcs[(size_t)(j+0)*HD] + pcs[(size_t)(j+1)*HD]
                 + pcs[(size_t)(j+2)*HD] + pcs[(size_t)(j+3)*HD];
        for (; j < c; j++) run += pcs[(size_t)j*HD];
    }

    float ga = gamma[tid], be = beta[tid];
    unsigned short* pch = g_csumh + base;
    unsigned short* pxh = g_xh + base;

    // phase 1: per-token per-warp partial (sum, sumsq)
    float r1 = run;
    #pragma unroll
    for (int i = 0; i < CC; i++) {
        float val = r1;
        r1 += xr[i];
        float s = val, q = val*val;
        #pragma unroll
        for (int o = 16; o; o >>= 1) {
            s += __shfl_xor_sync(0xffffffffu, s, o);
            q += __shfl_xor_sync(0xffffffffu, q, o);
        }
        if (lane == 0) { sm_s[warp][i] = s; sm_q[warp][i] = q; }
    }
    __syncthreads();

    // phase 2: reduce 16 warp-partials per token
    {
        int t = tid >> 4, k = tid & 15;
        float s = sm_s[k][t], q = sm_q[k][t];
        #pragma unroll
        for (int o = 8; o; o >>= 1) {
            s += __shfl_xor_sync(0xffffffffu, s, o);
            q += __shfl_xor_sync(0xffffffffu, q, o);
        }
        if (k == 0) {
            float m = s * (1.f/512.f);
            float v = q * (1.f/512.f) - m*m;
            sm_mean[t] = m;
            sm_inv[t]  = rsqrtf(v + 1e-5f);
        }
    }
    __syncthreads();

    // phase 3: rewalk from registers; write fp16 csum + fp16 x
    float r2 = run;
    #pragma unroll
    for (int i = 0; i < CC; i++) {
        float val = r2;
        r2 += xr[i];
        float cs = (val - sm_mean[i]) * sm_inv[i] * ga + be;
        pch[(size_t)i*HD] = __half_as_ushort(__float2half_rn(cs));
        pxh[(size_t)i*HD] = __half_as_ushort(__float2half_rn(xr[i]));
    }
}

// ================= A tile convert for GEMM1 ===================================
#define APITCH 136
#define A64_SMEM_BYTES (64*APITCH*2)      // 17408
#define A256_SMEM_BYTES (256*APITCH*2)    // 69632

// 64-row tile, 512 threads: r = tid>>3, q = tid&7 (16 halves each). Pure copy.
__device__ __forceinline__ void convert_A64(unsigned short* Ah, int row0, int tid) {
    int r = tid >> 3;
    int q = tid & 7;
    const unsigned short* src = (q < 4)
        ? (g_xh    + (size_t)(row0 + r)*64 + q*16)
        : (g_csumh + (size_t)(row0 + r)*64 + (q-4)*16);
    int kbase = q*16;
    uint4 v0 = *(const uint4*)src;
    uint4 v1 = *(const uint4*)(src + 8);
    *(uint4*)&Ah[r*APITCH + kbase]     = v0;
    *(uint4*)&Ah[r*APITCH + kbase + 8] = v1;
}

// ================= K4: GEMM1 via mma.sync + fused gates =======================
// Block: 512 thr (16 warps), M-tile 64. Warp = slab(4)*16 rows x nquad(4)*48 cols.
__global__ __launch_bounds__(512, 2) void k4_mma(const float* __restrict__ bhid) {
    extern __shared__ unsigned short smu[];
    unsigned short* Ah = smu;
    int tid = threadIdx.x, lane = tid & 31, wid = tid >> 5;
    int row0 = blockIdx.x * 64;

    convert_A64(Ah, row0, tid);
    __syncthreads();

    int slab = wid >> 2, nquad = wid & 3;
    int m0 = slab*16 + (lane >> 2);
    int kq = (lane & 3)*2;

    float c[6][4];
    #pragma unroll
    for (int j = 0; j < 6; j++)
        #pragma unroll
        for (int e = 0; e < 4; e++) c[j][e] = 0.f;

    #pragma unroll
    for (int ks = 0; ks < 8; ks++) {
        int ka = ks*16 + kq;
        uint32_t a0 = *(const uint32_t*)&Ah[m0*APITCH + ka];
        uint32_t a1 = *(const uint32_t*)&Ah[(m0+8)*APITCH + ka];
        uint32_t a2 = *(const uint32_t*)&Ah[m0*APITCH + ka + 8];
        uint32_t a3 = *(const uint32_t*)&Ah[(m0+8)*APITCH + ka + 8];
        const uint32_t* bb = g_WhF + ((size_t)(ks*24 + nquad*6)*32 + lane)*2;
        #pragma unroll
        for (int nt = 0; nt < 6; nt++) {
            uint2 b2 = *(const uint2*)(bb + nt*64);
            MMA4(c[nt], a0, a1, a2, a3, b2.x, b2.y);
        }
    }

    // epilogue: gate triple for d at c[dt], c[dt+2], c[dt+4]; pack half2(fg, igh)
    int u0 = (lane & 3)*2;
    int rbase = row0 + slab*16 + (lane >> 2);
    #pragma unroll
    for (int dt = 0; dt < 2; dt++) {
        int d = nquad*16 + dt*8 + u0;
        float bi0 = bhid[d],       bi1 = bhid[d+1];
        float bf0 = bhid[64 + d],  bf1 = bhid[64 + d + 1];
        float bq0 = bhid[128 + d], bq1 = bhid[128 + d + 1];
        #pragma unroll
        for (int h = 0; h < 2; h++) {
            int row = rbase + h*8;
            float i0 = c[dt][h*2]   + bi0, i1 = c[dt][h*2+1]   + bi1;
            float f0 = c[dt+2][h*2] + bf0, f1 = c[dt+2][h*2+1] + bf1;
            float q0 = c[dt+4][h*2] + bq0, q1 = c[dt+4][h*2+1] + bq1;
            float fg0 = sigmoidf_(f0), fg1 = sigmoidf_(f1);
            float ig0 = sigmoidf_(i0) * fmaxf(q0, 0.f);
            float ig1 = sigmoidf_(i1) * fmaxf(q1, 0.f);
            uint2 pk;
            __half2 p0 = __floats2half2_rn(fg0, ig0);
            __half2 p1 = __floats2half2_rn(fg1, ig1);
            pk.x = *(uint32_t*)&p0;
            pk.y = *(uint32_t*)&p1;
            *(uint2*)&g_fgi[(size_t)row*64 + d] = pk;
        }
    }
}

// ================= K7: fused cell-scan + GEMM2 + output gate ==================
// Block bc covers CC=32 tokens x 8 heads = 256 gemm rows. 512 thr (16 warps).
// Phase A (scan): tid = (h,d); fgi cached in regs; replay writes cell fp16 into
// the SMEM A-tile's upper K-half. Phase B: copy xh into lower K-half. Phase C:
// GEMM2 (warp = 16 rows x 64 cols) + fused sigmoid epilogue (cell from SMEM).
__global__ __launch_bounds__(512, 2) void k7_fused(const float* __restrict__ initcx,
                                                   const float* __restrict__ bog,
                                                   float* __restrict__ out) {
    extern __shared__ unsigned short smu[];
    unsigned short* Ah = smu;
    int tid = threadIdx.x, lane = tid & 31, wid = tid >> 5;
    int bc = blockIdx.x;
    int b = bc / NC, c = bc % NC;
    int rowg0 = (b*SS + c*CC)*HH;            // first gemm row of this block

    size_t base = ((size_t)(b*SS + c*CC))*HD + tid;

    // --- Phase A: pass 0 with fgi cached in registers ---
    uint32_t fr[CC];
    {
        const uint32_t* pfi = g_fgi + base;
        #pragma unroll
        for (int i = 0; i < CC; i++) fr[i] = pfi[(size_t)i*HD];
    }
    float a = 1.f, bv = 0.f;
    #pragma unroll
    for (int i = 0; i < CC; i++) {
        float2 fg = __half22float2(*(const __half2*)&fr[i]);
        a *= fg.x;
        bv = bv * fg.x + fg.y;
    }
    g_AB[(size_t)bc*HD + tid] = make_float2(a, bv);
    __threadfence();
    __syncthreads();
    if (tid == 0) atomicExch(&g_flag2[bc], 1);

    // lookback
    if (tid < c) {
        while (atomicAdd(&g_flag2[b*NC + tid], 0) == 0) __nanosleep(64);
        __threadfence();
    }
    __syncthreads();

    float carry = initcx[tid];
    {
        const float2* pAB = g_AB + (size_t)b*NC*HD + tid;
        int j = 0;
        for (; j + 8 <= c; j += 8) {
            float2 ab[8];
            #pragma unroll
            for (int u = 0; u < 8; u++) ab[u] = pAB[(size_t)(j+u)*HD];
            #pragma unroll
            for (int u = 0; u < 8; u++)
                carry = ab[u].x * carry + ab[u].y;
        }
        for (; j < c; j++) {
            float2 ab = pAB[(size_t)j*HD];
            carry = ab.x * carry + ab.y;
        }
    }

    // replay from registers -> SMEM A-tile upper K-half (cell fp16)
    {
        int h = tid >> 6, d = tid & 63;
        float cell = carry;
        #pragma unroll
        for (int i = 0; i < CC; i++) {
            float2 fg = __half22float2(*(const __half2*)&fr[i]);
            cell = fg.x * cell + fg.y;
            Ah[(i*8 + h)*APITCH + 64 + d] = __half_as_ushort(__float2half_rn(cell));
        }
    }

    // --- Phase B: copy xh into lower K-half ---
    {
        int r = tid >> 1, q = tid & 1;            // 256 rows, 32 halves each
        const unsigned short* src = g_xh + (size_t)(rowg0 + r)*64 + q*32;
        #pragma unroll
        for (int i = 0; i < 4; i++)
            *(uint4*)&Ah[r*APITCH + q*32 + i*8] = *(const uint4*)(src + i*8);
    }
    __syncthreads();

    // --- Phase C: GEMM2, warp = rows wid*16..+16, all 64 cols ---
    int m0 = wid*16 + (lane >> 2);
    int kq = (lane & 3)*2;

    float cacc[8][4];
    #pragma unroll
    for (int j = 0; j < 8; j++)
        #pragma unroll
        for (int e = 0; e < 4; e++) cacc[j][e] = 0.f;

    #pragma unroll
    for (int ks = 0; ks < 8; ks++) {
        int ka = ks*16 + kq;
        uint32_t a0 = *(const uint32_t*)&Ah[m0*APITCH + ka];
        uint32_t a1 = *(const uint32_t*)&Ah[(m0+8)*APITCH + ka];
        uint32_t a2 = *(const uint32_t*)&Ah[m0*APITCH + ka + 8];
        uint32_t a3 = *(const uint32_t*)&Ah[(m0+8)*APITCH + ka + 8];
        const uint32_t* bb = g_WoF + ((size_t)(ks*8)*32 + lane)*2;
        #pragma unroll
        for (int nt = 0; nt < 8; nt++) {
            uint2 b2 = *(const uint2*)(bb + nt*64);
            MMA4(cacc[nt], a0, a1, a2, a3, b2.x, b2.y);
        }
    }

    int u0 = (lane & 3)*2;
    #pragma unroll
    for (int nt = 0; nt < 8; nt++) {
        int d = nt*8 + u0;
        float b0 = bog[d], b1 = bog[d+1];
        #pragma unroll
        for (int h = 0; h < 2; h++) {
            int rloc = wid*16 + (lane >> 2) + h*8;
            float2 cv = __half22float2(*(const __half2*)&Ah[rloc*APITCH + 64 + d]);
            float2 ov;
            ov.x = sigmoidf_(cacc[nt][h*2]   + b0) * cv.x;
            ov.y = sigmoidf_(cacc[nt][h*2+1] + b1) * cv.y;
            *(float2*)&out[(size_t)(rowg0 + rloc)*64 + d] = ov;
        }
    }
}

// ================= launch =====================================================
extern "C" void kernel_launch(void* const* d_in, const int* in_sizes, int n_in,
                              void* d_out, int out_size) {
    const float* x      = (const float*)d_in[0];
    const float* Wh     = (const float*)d_in[1];
    const float* bh     = (const float*)d_in[2];
    const float* Wog    = (const float*)d_in[3];
    const float* bog    = (const float*)d_in[4];
    const float* gamma  = (const float*)d_in[5];
    const float* beta   = (const float*)d_in[6];
    const float* initcx = (const float*)d_in[7];
    float* out = (float*)d_out;

    static bool attr_done = false;
    if (!attr_done) {
        cudaFuncSetAttribute(k4_mma,   cudaFuncAttributeMaxDynamicSharedMemorySize, A64_SMEM_BYTES);
        cudaFuncSetAttribute(k7_fused, cudaFuncAttributeMaxDynamicSharedMemorySize, A256_SMEM_BYTES);
        attr_done = true;
    }

    kprep_w<<<48, 256>>>(Wh, Wog);
    k3_csum_ln<<<BC, 512>>>(x, gamma, beta);
    k4_mma<<<ROWS/64, 512, A64_SMEM_BYTES>>>(bh);
    k7_fused<<<BC, 512, A256_SMEM_BYTES>>>(initcx, bog, out);
}

// round 15
// speedup vs baseline: 1.5875x; 1.0284x over previous
#include <cuda_runtime.h>
#include <cuda_bf16.h>
#include <cuda_fp16.h>
#include <cstdint>

// Problem dims
#define BB 4
#define SS 4096
#define HH 8
#define DD 64
#define HD 512
#define TOK (BB*SS)
#define ROWS (TOK*HH)          // 131072 gemm rows
#define CC 32
#define NC (SS/CC)
#define BC (BB*NC)

#define GRID_K3 BC             // 512
#define GRID_K4 (ROWS/64)      // 2048
#define GRID_K7 BC             // 512

// ================= scratch ====================================================
__device__ unsigned short g_xh   [ROWS*DD];   // x in fp16
__device__ unsigned short g_csumh[ROWS*DD];   // normalized csum in fp16
__device__ uint32_t g_fgi[ROWS*DD];           // packed half2(fg, igh)
__device__ float g_chunksum[BC*HD];
__device__ float2 g_AB[BC*HD];                // packed (A, Bv)
__device__ int   g_flag1[BC];                 // k3 chunksum published
__device__ int   g_flag2[BC];                 // k7 chunk state published
__device__ int   g_flag3[BC];                 // k3 outputs (xh/csumh) ready
__device__ int   g_cnt4 [BC];                 // k4 tiles done per chunk (target 4)
// W pre-packed in mma B-fragment order: [ks][nt][lane][2] u32 (fp16x2 each)
__device__ uint32_t g_WhF[12288];
__device__ uint32_t g_WoF[4096];

// ================= helpers ====================================================
__device__ __forceinline__ float sigmoidf_(float v) { return 1.f / (1.f + __expf(-v)); }

#define MMA4(c, a0,a1,a2,a3, b0,b1) \
    asm volatile("mma.sync.aligned.m16n8k16.row.col.f32.f16.f16.f32 " \
        "{%0,%1,%2,%3}, {%4,%5,%6,%7}, {%8,%9}, {%0,%1,%2,%3};" \
        : "+f"((c)[0]),"+f"((c)[1]),"+f"((c)[2]),"+f"((c)[3]) \
        : "r"(a0),"r"(a1),"r"(a2),"r"(a3),"r"(b0),"r"(b1))

// ================= prep: flag reset + W -> B-fragment images ==================
__global__ void kprep_w(const float* __restrict__ Wh, const float* __restrict__ Wog) {
    int t = blockIdx.x * blockDim.x + threadIdx.x;
    int stride = gridDim.x * blockDim.x;
    for (int i = t; i < BC; i += stride) {
        g_flag1[i] = 0; g_flag2[i] = 0; g_flag3[i] = 0; g_cnt4[i] = 0;
    }
    for (int idx = t; idx < 12288; idx += stride) {
        int reg  = idx & 1;
        int lane = (idx >> 1) & 31;
        int nt   = (idx >> 6) % 24;
        int ks   = (idx >> 6) / 24;
        int nquad = nt / 6, ntl = nt % 6;
        int gate = ntl >> 1, dt = ntl & 1;
        int d = nquad*16 + dt*8 + (lane >> 2);
        int n = gate*64 + d;
        int k0 = ks*16 + (lane & 3)*2 + reg*8;
        unsigned short h0 = __half_as_ushort(__float2half_rn(Wh[(size_t)k0*192 + n]));
        unsigned short h1 = __half_as_ushort(__float2half_rn(Wh[(size_t)(k0+1)*192 + n]));
        g_WhF[idx] = (uint32_t)h0 | ((uint32_t)h1 << 16);
    }
    for (int idx = t; idx < 4096; idx += stride) {
        int reg  = idx & 1;
        int lane = (idx >> 1) & 31;
        int nt   = (idx >> 6) % 8;
        int ks   = (idx >> 6) / 8;
        int n = nt*8 + (lane >> 2);
        int k0 = ks*16 + (lane & 3)*2 + reg*8;
        unsigned short h0 = __half_as_ushort(__float2half_rn(Wog[(size_t)k0*64 + n]));
        unsigned short h1 = __half_as_ushort(__float2half_rn(Wog[(size_t)(k0+1)*64 + n]));
        g_WoF[idx] = (uint32_t)h0 | ((uint32_t)h1 << 16);
    }
}

#define APITCH 136
#define MEGA_SMEM_BYTES (256*APITCH*2)    // 69632 (k7 tile; k4 uses a prefix)

// ================= mega kernel: k3 | k4 | k7 by block id ======================
__global__ __launch_bounds__(512, 2) void k_mega(const float* __restrict__ x,
                                                 const float* __restrict__ gamma,
                                                 const float* __restrict__ beta,
                                                 const float* __restrict__ bhid,
                                                 const float* __restrict__ initcx,
                                                 const float* __restrict__ bog,
                                                 float* __restrict__ out) {
    extern __shared__ unsigned short smu[];
    int bid = blockIdx.x;
    int tid = threadIdx.x, lane = tid & 31, wid = tid >> 5;

    if (bid < GRID_K3) {
        // =============== K3 body: chunk-sum + lookback + cumsum + LN ==========
        int bc = bid;
        int b = bc / NC, c = bc % NC;
        int warp = wid;
        __shared__ float sm_s[16][33];
        __shared__ float sm_q[16][33];
        __shared__ float sm_mean[32], sm_inv[32];

        size_t base = ((size_t)(b*SS + c*CC))*HD + tid;
        const float* px = x + base;

        float xr[CC];
        float sown = 0.f;
        #pragma unroll
        for (int i = 0; i < CC; i++) { xr[i] = px[(size_t)i*HD]; sown += xr[i]; }
        g_chunksum[(size_t)bc*HD + tid] = sown;
        __threadfence();
        __syncthreads();
        if (tid == 0) atomicExch(&g_flag1[bc], 1);

        if (tid < c) {
            while (atomicAdd(&g_flag1[b*NC + tid], 0) == 0) __nanosleep(64);
            __threadfence();
        }
        __syncthreads();

        float run = 0.f;
        {
            const float* pcs = g_chunksum + (size_t)b*NC*HD + tid;
            int j = 0;
            for (; j + 4 <= c; j += 4)
                run += pcs[(size_t)(j+0)*HD] + pcs[(size_t)(j+1)*HD]
                     + pcs[(size_t)(j+2)*HD] + pcs[(size_t)(j+3)*HD];
            for (; j < c; j++) run += pcs[(size_t)j*HD];
        }

        float ga = gamma[tid], be = beta[tid];
        unsigned short* pch = g_csumh + base;
        unsigned short* pxh = g_xh + base;

        float r1 = run;
        #pragma unroll
        for (int i = 0; i < CC; i++) {
            float val = r1;
            r1 += xr[i];
            float s = val, q = val*val;
            #pragma unroll
            for (int o = 16; o; o >>= 1) {
                s += __shfl_xor_sync(0xffffffffu, s, o);
                q += __shfl_xor_sync(0xffffffffu, q, o);
            }
            if (lane == 0) { sm_s[warp][i] = s; sm_q[warp][i] = q; }
        }
        __syncthreads();

        {
            int t = tid >> 4, k = tid & 15;
            float s = sm_s[k][t], q = sm_q[k][t];
            #pragma unroll
            for (int o = 8; o; o >>= 1) {
                s += __shfl_xor_sync(0xffffffffu, s, o);
                q += __shfl_xor_sync(0xffffffffu, q, o);
            }
            if (k == 0) {
                float m = s * (1.f/512.f);
                float v = q * (1.f/512.f) - m*m;
                sm_mean[t] = m;
                sm_inv[t]  = rsqrtf(v + 1e-5f);
            }
        }
        __syncthreads();

        float r2 = run;
        #pragma unroll
        for (int i = 0; i < CC; i++) {
            float val = r2;
            r2 += xr[i];
            float cs = (val - sm_mean[i]) * sm_inv[i] * ga + be;
            pch[(size_t)i*HD] = __half_as_ushort(__float2half_rn(cs));
            pxh[(size_t)i*HD] = __half_as_ushort(__float2half_rn(xr[i]));
        }
        __threadfence();
        __syncthreads();
        if (tid == 0) atomicExch(&g_flag3[bc], 1);

    } else if (bid < GRID_K3 + GRID_K4) {
        // =============== K4 body: GEMM1 + fused gates =========================
        int bid4 = bid - GRID_K3;
        int row0 = bid4 * 64;
        int bc = bid4 >> 2;            // owning chunk (8 tokens within 32-chunk)

        // wait for k3 outputs of this chunk
        if (tid == 0) {
            while (atomicAdd(&g_flag3[bc], 0) == 0) __nanosleep(128);
            __threadfence();
        }
        __syncthreads();

        unsigned short* Ah = smu;
        {
            int r = tid >> 3;
            int q = tid & 7;
            const unsigned short* src = (q < 4)
                ? (g_xh    + (size_t)(row0 + r)*64 + q*16)
                : (g_csumh + (size_t)(row0 + r)*64 + (q-4)*16);
            int kbase = q*16;
            uint4 v0 = *(const uint4*)src;
            uint4 v1 = *(const uint4*)(src + 8);
            *(uint4*)&Ah[r*APITCH + kbase]     = v0;
            *(uint4*)&Ah[r*APITCH + kbase + 8] = v1;
        }
        __syncthreads();

        int slab = wid >> 2, nquad = wid & 3;
        int m0 = slab*16 + (lane >> 2);
        int kq = (lane & 3)*2;

        float c4[6][4];
        #pragma unroll
        for (int j = 0; j < 6; j++)
            #pragma unroll
            for (int e = 0; e < 4; e++) c4[j][e] = 0.f;

        #pragma unroll
        for (int ks = 0; ks < 8; ks++) {
            int ka = ks*16 + kq;
            uint32_t a0 = *(const uint32_t*)&Ah[m0*APITCH + ka];
            uint32_t a1 = *(const uint32_t*)&Ah[(m0+8)*APITCH + ka];
            uint32_t a2 = *(const uint32_t*)&Ah[m0*APITCH + ka + 8];
            uint32_t a3 = *(const uint32_t*)&Ah[(m0+8)*APITCH + ka + 8];
            const uint32_t* bb = g_WhF + ((size_t)(ks*24 + nquad*6)*32 + lane)*2;
            #pragma unroll
            for (int nt = 0; nt < 6; nt++) {
                uint2 b2 = *(const uint2*)(bb + nt*64);
                MMA4(c4[nt], a0, a1, a2, a3, b2.x, b2.y);
            }
        }

        int u0 = (lane & 3)*2;
        int rbase = row0 + slab*16 + (lane >> 2);
        #pragma unroll
        for (int dt = 0; dt < 2; dt++) {
            int d = nquad*16 + dt*8 + u0;
            float bi0 = bhid[d],       bi1 = bhid[d+1];
            float bf0 = bhid[64 + d],  bf1 = bhid[64 + d + 1];
            float bq0 = bhid[128 + d], bq1 = bhid[128 + d + 1];
            #pragma unroll
            for (int h = 0; h < 2; h++) {
                int row = rbase + h*8;
                float i0 = c4[dt][h*2]   + bi0, i1 = c4[dt][h*2+1]   + bi1;
                float f0 = c4[dt+2][h*2] + bf0, f1 = c4[dt+2][h*2+1] + bf1;
                float q0 = c4[dt+4][h*2] + bq0, q1 = c4[dt+4][h*2+1] + bq1;
                float fg0 = sigmoidf_(f0), fg1 = sigmoidf_(f1);
                float ig0 = sigmoidf_(i0) * fmaxf(q0, 0.f);
                float ig1 = sigmoidf_(i1) * fmaxf(q1, 0.f);
                uint2 pk;
                __half2 p0 = __floats2half2_rn(fg0, ig0);
                __half2 p1 = __floats2half2_rn(fg1, ig1);
                pk.x = *(uint32_t*)&p0;
                pk.y = *(uint32_t*)&p1;
                *(uint2*)&g_fgi[(size_t)row*64 + d] = pk;
            }
        }
        __threadfence();
        __syncthreads();
        if (tid == 0) atomicAdd(&g_cnt4[bc], 1);

    } else {
        // =============== K7 body: cell scan + GEMM2 + output gate =============
        int bc = bid - GRID_K3 - GRID_K4;
        int b = bc / NC, c = bc % NC;
        int rowg0 = (b*SS + c*CC)*HH;
        unsigned short* Ah = smu;

        // wait for all 4 k4 tiles of this chunk
        if (tid == 0) {
            while (atomicAdd(&g_cnt4[bc], 0) < 4) __nanosleep(128);
            __threadfence();
        }
        __syncthreads();

        size_t base = ((size_t)(b*SS + c*CC))*HD + tid;

        // fgi cached in registers
        uint32_t fr[CC];
        {
            const uint32_t* pfi = g_fgi + base;
            #pragma unroll
            for (int i = 0; i < CC; i++) fr[i] = pfi[(size_t)i*HD];
        }

        // xh -> SMEM lower K-half (independent; overlaps with spin below)
        {
            int r = tid >> 1, q = tid & 1;
            const unsigned short* src = g_xh + (size_t)(rowg0 + r)*64 + q*32;
            #pragma unroll
            for (int i = 0; i < 4; i++)
                *(uint4*)&Ah[r*APITCH + q*32 + i*8] = *(const uint4*)(src + i*8);
        }

        float a = 1.f, bv = 0.f;
        #pragma unroll
        for (int i = 0; i < CC; i++) {
            float2 fg = __half22float2(*(const __half2*)&fr[i]);
            a *= fg.x;
            bv = bv * fg.x + fg.y;
        }
        g_AB[(size_t)bc*HD + tid] = make_float2(a, bv);
        __threadfence();
        __syncthreads();
        if (tid == 0) atomicExch(&g_flag2[bc], 1);

        if (tid < c) {
            while (atomicAdd(&g_flag2[b*NC + tid], 0) == 0) __nanosleep(64);
            __threadfence();
        }
        __syncthreads();

        float carry = initcx[tid];
        {
            const float2* pAB = g_AB + (size_t)b*NC*HD + tid;
            int j = 0;
            for (; j + 8 <= c; j += 8) {
                float2 ab[8];
                #pragma unroll
                for (int u = 0; u < 8; u++) ab[u] = pAB[(size_t)(j+u)*HD];
                #pragma unroll
                for (int u = 0; u < 8; u++)
                    carry = ab[u].x * carry + ab[u].y;
            }
            for (; j < c; j++) {
                float2 ab = pAB[(size_t)j*HD];
                carry = ab.x * carry + ab.y;
            }
        }

        // replay -> SMEM upper K-half (cell fp16)
        {
            int h = tid >> 6, d = tid & 63;
            float cell = carry;
            #pragma unroll
            for (int i = 0; i < CC; i++) {
                float2 fg = __half22float2(*(const __half2*)&fr[i]);
                cell = fg.x * cell + fg.y;
                Ah[(i*8 + h)*APITCH + 64 + d] = __half_as_ushort(__float2half_rn(cell));
            }
        }
        __syncthreads();

        // GEMM2: warp = rows wid*16..+16, all 64 cols
        int m0 = wid*16 + (lane >> 2);
        int kq = (lane & 3)*2;

        float cacc[8][4];
        #pragma unroll
        for (int j = 0; j < 8; j++)
            #pragma unroll
            for (int e = 0; e < 4; e++) cacc[j][e] = 0.f;

        #pragma unroll
        for (int ks = 0; ks < 8; ks++) {
            int ka = ks*16 + kq;
            uint32_t a0 = *(const uint32_t*)&Ah[m0*APITCH + ka];
            uint32_t a1 = *(const uint32_t*)&Ah[(m0+8)*APITCH + ka];
            uint32_t a2 = *(const uint32_t*)&Ah[m0*APITCH + ka + 8];
            uint32_t a3 = *(const uint32_t*)&Ah[(m0+8)*APITCH + ka + 8];
            const uint32_t* bb = g_WoF + ((size_t)(ks*8)*32 + lane)*2;
            #pragma unroll
            for (int nt = 0; nt < 8; nt++) {
                uint2 b2 = *(const uint2*)(bb + nt*64);
                MMA4(cacc[nt], a0, a1, a2, a3, b2.x, b2.y);
            }
        }

        int u0 = (lane & 3)*2;
        #pragma unroll
        for (int nt = 0; nt < 8; nt++) {
            int d = nt*8 + u0;
            float b0 = bog[d], b1 = bog[d+1];
            #pragma unroll
            for (int h = 0; h < 2; h++) {
                int rloc = wid*16 + (lane >> 2) + h*8;
                float2 cv = __half22float2(*(const __half2*)&Ah[rloc*APITCH + 64 + d]);
                float2 ov;
                ov.x = sigmoidf_(cacc[nt][h*2]   + b0) * cv.x;
                ov.y = sigmoidf_(cacc[nt][h*2+1] + b1) * cv.y;
                *(float2*)&out[(size_t)(rowg0 + rloc)*64 + d] = ov;
            }
        }
    }
}

// ================= launch =====================================================
extern "C" void kernel_launch(void* const* d_in, const int* in_sizes, int n_in,
                              void* d_out, int out_size) {
    const float* x      = (const float*)d_in[0];
    const float* Wh     = (const float*)d_in[1];
    const float* bh     = (const float*)d_in[2];
    const float* Wog    = (const float*)d_in[3];
    const float* bog    = (const float*)d_in[4];
    const float* gamma  = (const float*)d_in[5];
    const float* beta   = (const float*)d_in[6];
    const float* initcx = (const float*)d_in[7];
    float* out = (float*)d_out;

    static bool attr_done = false;
    if (!attr_done) {
        cudaFuncSetAttribute(k_mega, cudaFuncAttributeMaxDynamicSharedMemorySize, MEGA_SMEM_BYTES);
        attr_done = true;
    }

    kprep_w<<<48, 256>>>(Wh, Wog);
    k_mega<<<GRID_K3 + GRID_K4 + GRID_K7, 512, MEGA_SMEM_BYTES>>>(
        x, gamma, beta, bh, initcx, bog, out);
}

// round 17
// speedup vs baseline: 1.7843x; 1.1240x over previous
#include <cuda_runtime.h>
#include <cuda_bf16.h>
#include <cuda_fp16.h>
#include <cstdint>

// Problem dims
#define BB 4
#define SS 4096
#define HH 8
#define DD 64
#define HD 512
#define TOK (BB*SS)
#define ROWS (TOK*HH)          // 131072 gemm rows
#define CC 32
#define NC (SS/CC)
#define BC (BB*NC)

#define GRID_K34 BC            // 512 fused k3+k4 blocks
#define GRID_K7  BC            // 512 k7 blocks

// ================= scratch ====================================================
__device__ unsigned short g_xh[ROWS*DD];      // x in fp16 (for k7 only)
__device__ uint32_t g_fgi[ROWS*DD];           // packed half2(fg, igh)
__device__ float g_chunksum[BC*HD];
__device__ float2 g_AB[BC*HD];                // packed (A, Bv)
__device__ int   g_flag1[BC];                 // k3 chunksum published
__device__ int   g_flag2[BC];                 // k7 chunk state published
__device__ int   g_flag3[BC];                 // chunk fgi+xh ready
// W pre-packed in mma B-fragment order: [ks][nt][lane][2] u32 (fp16x2 each)
__device__ uint32_t g_WhF[12288];
__device__ uint32_t g_WoF[4096];

// ================= helpers ====================================================
__device__ __forceinline__ float sigmoidf_(float v) { return 1.f / (1.f + __expf(-v)); }

#define MMA4(c, a0,a1,a2,a3, b0,b1) \
    asm volatile("mma.sync.aligned.m16n8k16.row.col.f32.f16.f16.f32 " \
        "{%0,%1,%2,%3}, {%4,%5,%6,%7}, {%8,%9}, {%0,%1,%2,%3};" \
        : "+f"((c)[0]),"+f"((c)[1]),"+f"((c)[2]),"+f"((c)[3]) \
        : "r"(a0),"r"(a1),"r"(a2),"r"(a3),"r"(b0),"r"(b1))

// ================= prep: flag reset + W -> B-fragment images ==================
__global__ void kprep_w(const float* __restrict__ Wh, const float* __restrict__ Wog) {
    int t = blockIdx.x * blockDim.x + threadIdx.x;
    int stride = gridDim.x * blockDim.x;
    for (int i = t; i < BC; i += stride) {
        g_flag1[i] = 0; g_flag2[i] = 0; g_flag3[i] = 0;
    }
    for (int idx = t; idx < 12288; idx += stride) {
        int reg  = idx & 1;
        int lane = (idx >> 1) & 31;
        int nt   = (idx >> 6) % 24;
        int ks   = (idx >> 6) / 24;
        int nquad = nt / 6, ntl = nt % 6;
        int gate = ntl >> 1, dt = ntl & 1;
        int d = nquad*16 + dt*8 + (lane >> 2);
        int n = gate*64 + d;
        int k0 = ks*16 + (lane & 3)*2 + reg*8;
        unsigned short h0 = __half_as_ushort(__float2half_rn(Wh[(size_t)k0*192 + n]));
        unsigned short h1 = __half_as_ushort(__float2half_rn(Wh[(size_t)(k0+1)*192 + n]));
        g_WhF[idx] = (uint32_t)h0 | ((uint32_t)h1 << 16);
    }
    for (int idx = t; idx < 4096; idx += stride) {
        int reg  = idx & 1;
        int lane = (idx >> 1) & 31;
        int nt   = (idx >> 6) % 8;
        int ks   = (idx >> 6) / 8;
        int n = nt*8 + (lane >> 2);
        int k0 = ks*16 + (lane & 3)*2 + reg*8;
        unsigned short h0 = __half_as_ushort(__float2half_rn(Wog[(size_t)k0*64 + n]));
        unsigned short h1 = __half_as_ushort(__float2half_rn(Wog[(size_t)(k0+1)*64 + n]));
        g_WoF[idx] = (uint32_t)h0 | ((uint32_t)h1 << 16);
    }
}

#define APITCH 136
#define MEGA_SMEM_BYTES (256*APITCH*2)    // 69632

// ================= mega kernel: fused k3+k4 | k7 by block id ==================
__global__ __launch_bounds__(512, 2) void k_mega(const float* __restrict__ x,
                                                 const float* __restrict__ gamma,
                                                 const float* __restrict__ beta,
                                                 const float* __restrict__ bhid,
                                                 const float* __restrict__ initcx,
                                                 const float* __restrict__ bog,
                                                 float* __restrict__ out) {
    extern __shared__ unsigned short smu[];
    unsigned short* Ah = smu;
    __shared__ float sm_s[16][33];
    __shared__ float sm_q[16][33];
    __shared__ float sm_mean[32], sm_inv[32];
    int bid = blockIdx.x;
    int tid = threadIdx.x, lane = tid & 31, wid = tid >> 5;

    if (bid < GRID_K34) {
        // ====== fused K3+K4: LN scan -> SMEM A-tile -> 4x GEMM1 sub-tiles =====
        int bc = bid;
        int b = bc / NC, c = bc % NC;
        int rowg0 = (b*SS + c*CC)*HH;

        size_t base = ((size_t)(b*SS + c*CC))*HD + tid;
        const float* px = x + base;
        int hh = tid >> 6, dd = tid & 63;     // tid = (h, d)

        // --- phase 0: x slice to regs; chunk sum; publish ---
        float xr[CC];
        {
            float sown = 0.f;
            #pragma unroll
            for (int i = 0; i < CC; i++) { xr[i] = px[(size_t)i*HD]; sown += xr[i]; }
            g_chunksum[(size_t)bc*HD + tid] = sown;
        }
        __threadfence();
        __syncthreads();
        if (tid == 0) atomicExch(&g_flag1[bc], 1);

        if (tid < c) {
            while (atomicAdd(&g_flag1[b*NC + tid], 0) == 0) __nanosleep(64);
            __threadfence();
        }
        __syncthreads();

        float run = 0.f;
        {
            const float* pcs = g_chunksum + (size_t)b*NC*HD + tid;
            int j = 0;
            for (; j + 4 <= c; j += 4)
                run += pcs[(size_t)(j+0)*HD] + pcs[(size_t)(j+1)*HD]
                     + pcs[(size_t)(j+2)*HD] + pcs[(size_t)(j+3)*HD];
            for (; j < c; j++) run += pcs[(size_t)j*HD];
        }

        // --- phase 1: per-token per-warp partials ---
        {
            float r1 = run;
            #pragma unroll
            for (int i = 0; i < CC; i++) {
                float val = r1;
                r1 += xr[i];
                float s = val, q = val*val;
                #pragma unroll
                for (int o = 16; o; o >>= 1) {
                    s += __shfl_xor_sync(0xffffffffu, s, o);
                    q += __shfl_xor_sync(0xffffffffu, q, o);
                }
                if (lane == 0) { sm_s[wid][i] = s; sm_q[wid][i] = q; }
            }
        }
        __syncthreads();

        // --- phase 2: reduce 16 warp-partials per token ---
        {
            int t = tid >> 4, k = tid & 15;
            float s = sm_s[k][t], q = sm_q[k][t];
            #pragma unroll
            for (int o = 8; o; o >>= 1) {
                s += __shfl_xor_sync(0xffffffffu, s, o);
                q += __shfl_xor_sync(0xffffffffu, q, o);
            }
            if (k == 0) {
                float m = s * (1.f/512.f);
                float v = q * (1.f/512.f) - m*m;
                sm_mean[t] = m;
                sm_inv[t]  = rsqrtf(v + 1e-5f);
            }
        }
        __syncthreads();

        // --- phase 3: write fp16 x/csum into SMEM A-tile + xh to global ---
        {
            float ga = gamma[tid], be = beta[tid];
            unsigned short* pxh = g_xh + base;
            float r2 = run;
            #pragma unroll
            for (int i = 0; i < CC; i++) {
                float val = r2;
                r2 += xr[i];
                float cs = (val - sm_mean[i]) * sm_inv[i] * ga + be;
                unsigned short xh16 = __half_as_ushort(__float2half_rn(xr[i]));
                int r = i*8 + hh;
                Ah[r*APITCH + dd]      = xh16;
                Ah[r*APITCH + 64 + dd] = __half_as_ushort(__float2half_rn(cs));
                pxh[(size_t)i*HD] = xh16;
            }
        }
        __syncthreads();

        // --- phase 4: GEMM1 over 4 sub-tiles of 64 rows ---
        int slab = wid >> 2, nquad = wid & 3;
        int kq = (lane & 3)*2;
        int u0 = (lane & 3)*2;

        #pragma unroll 1
        for (int t = 0; t < 4; t++) {
            int m0 = t*64 + slab*16 + (lane >> 2);

            float c4[6][4];
            #pragma unroll
            for (int j = 0; j < 6; j++)
                #pragma unroll
                for (int e = 0; e < 4; e++) c4[j][e] = 0.f;

            #pragma unroll
            for (int ks = 0; ks < 8; ks++) {
                int ka = ks*16 + kq;
                uint32_t a0 = *(const uint32_t*)&Ah[m0*APITCH + ka];
                uint32_t a1 = *(const uint32_t*)&Ah[(m0+8)*APITCH + ka];
                uint32_t a2 = *(const uint32_t*)&Ah[m0*APITCH + ka + 8];
                uint32_t a3 = *(const uint32_t*)&Ah[(m0+8)*APITCH + ka + 8];
                const uint32_t* bb = g_WhF + ((size_t)(ks*24 + nquad*6)*32 + lane)*2;
                #pragma unroll
                for (int nt = 0; nt < 6; nt++) {
                    uint2 b2 = *(const uint2*)(bb + nt*64);
                    MMA4(c4[nt], a0, a1, a2, a3, b2.x, b2.y);
                }
            }

            int rbase = rowg0 + t*64 + slab*16 + (lane >> 2);
            #pragma unroll
            for (int dt = 0; dt < 2; dt++) {
                int d = nquad*16 + dt*8 + u0;
                float bi0 = bhid[d],       bi1 = bhid[d+1];
                float bf0 = bhid[64 + d],  bf1 = bhid[64 + d + 1];
                float bq0 = bhid[128 + d], bq1 = bhid[128 + d + 1];
                #pragma unroll
                for (int h = 0; h < 2; h++) {
                    int row = rbase + h*8;
                    float i0 = c4[dt][h*2]   + bi0, i1 = c4[dt][h*2+1]   + bi1;
                    float f0 = c4[dt+2][h*2] + bf0, f1 = c4[dt+2][h*2+1] + bf1;
                    float q0 = c4[dt+4][h*2] + bq0, q1 = c4[dt+4][h*2+1] + bq1;
                    float fg0 = sigmoidf_(f0), fg1 = sigmoidf_(f1);
                    float ig0 = sigmoidf_(i0) * fmaxf(q0, 0.f);
                    float ig1 = sigmoidf_(i1) * fmaxf(q1, 0.f);
                    uint2 pk;
                    __half2 p0 = __floats2half2_rn(fg0, ig0);
                    __half2 p1 = __floats2half2_rn(fg1, ig1);
                    pk.x = *(uint32_t*)&p0;
                    pk.y = *(uint32_t*)&p1;
                    *(uint2*)&g_fgi[(size_t)row*64 + d] = pk;
                }
            }
        }
        __threadfence();
        __syncthreads();
        if (tid == 0) atomicExch(&g_flag3[bc], 1);

    } else {
        // =============== K7 body: cell scan + GEMM2 + output gate =============
        int bc = bid - GRID_K34;
        int b = bc / NC, c = bc % NC;
        int rowg0 = (b*SS + c*CC)*HH;

        // wait for this chunk's fgi/xh
        if (tid == 0) {
            while (atomicAdd(&g_flag3[bc], 0) == 0) __nanosleep(128);
            __threadfence();
        }
        __syncthreads();

        size_t base = ((size_t)(b*SS + c*CC))*HD + tid;

        // fgi cached in registers
        uint32_t fr[CC];
        {
            const uint32_t* pfi = g_fgi + base;
            #pragma unroll
            for (int i = 0; i < CC; i++) fr[i] = pfi[(size_t)i*HD];
        }

        // xh -> SMEM lower K-half
        {
            int r = tid >> 1, q = tid & 1;
            const unsigned short* src = g_xh + (size_t)(rowg0 + r)*64 + q*32;
            #pragma unroll
            for (int i = 0; i < 4; i++)
                *(uint4*)&Ah[r*APITCH + q*32 + i*8] = *(const uint4*)(src + i*8);
        }

        float a = 1.f, bv = 0.f;
        #pragma unroll
        for (int i = 0; i < CC; i++) {
            float2 fg = __half22float2(*(const __half2*)&fr[i]);
            a *= fg.x;
            bv = bv * fg.x + fg.y;
        }
        g_AB[(size_t)bc*HD + tid] = make_float2(a, bv);
        __threadfence();
        __syncthreads();
        if (tid == 0) atomicExch(&g_flag2[bc], 1);

        if (tid < c) {
            while (atomicAdd(&g_flag2[b*NC + tid], 0) == 0) __nanosleep(64);
            __threadfence();
        }
        __syncthreads();

        float carry = initcx[tid];
        {
            const float2* pAB = g_AB + (size_t)b*NC*HD + tid;
            int j = 0;
            for (; j + 8 <= c; j += 8) {
                float2 ab[8];
                #pragma unroll
                for (int u = 0; u < 8; u++) ab[u] = pAB[(size_t)(j+u)*HD];
                #pragma unroll
                for (int u = 0; u < 8; u++)
                    carry = ab[u].x * carry + ab[u].y;
            }
            for (; j < c; j++) {
                float2 ab = pAB[(size_t)j*HD];
                carry = ab.x * carry + ab.y;
            }
        }

        // replay -> SMEM upper K-half (cell fp16)
        {
            int h = tid >> 6, d = tid & 63;
            float cell = carry;
            #pragma unroll
            for (int i = 0; i < CC; i++) {
                float2 fg = __half22float2(*(const __half2*)&fr[i]);
                cell = fg.x * cell + fg.y;
                Ah[(i*8 + h)*APITCH + 64 + d] = __half_as_ushort(__float2half_rn(cell));
            }
        }
        __syncthreads();

        // GEMM2: warp = rows wid*16..+16, all 64 cols
        int m0 = wid*16 + (lane >> 2);
        int kq = (lane & 3)*2;

        float cacc[8][4];
        #pragma unroll
        for (int j = 0; j < 8; j++)
            #pragma unroll
            for (int e = 0; e < 4; e++) cacc[j][e] = 0.f;

        #pragma unroll
        for (int ks = 0; ks < 8; ks++) {
            int ka = ks*16 + kq;
            uint32_t a0 = *(const uint32_t*)&Ah[m0*APITCH + ka];
            uint32_t a1 = *(const uint32_t*)&Ah[(m0+8)*APITCH + ka];
            uint32_t a2 = *(const uint32_t*)&Ah[m0*APITCH + ka + 8];
            uint32_t a3 = *(const uint32_t*)&Ah[(m0+8)*APITCH + ka + 8];
            const uint32_t* bb = g_WoF + ((size_t)(ks*8)*32 + lane)*2;
            #pragma unroll
            for (int nt = 0; nt < 8; nt++) {
                uint2 b2 = *(const uint2*)(bb + nt*64);
                MMA4(cacc[nt], a0, a1, a2, a3, b2.x, b2.y);
            }
        }

        int u0 = (lane & 3)*2;
        #pragma unroll
        for (int nt = 0; nt < 8; nt++) {
            int d = nt*8 + u0;
            float b0 = bog[d], b1 = bog[d+1];
            #pragma unroll
            for (int h = 0; h < 2; h++) {
                int rloc = wid*16 + (lane >> 2) + h*8;
                float2 cv = __half22float2(*(const __half2*)&Ah[rloc*APITCH + 64 + d]);
                float2 ov;
                ov.x = sigmoidf_(cacc[nt][h*2]   + b0) * cv.x;
                ov.y = sigmoidf_(cacc[nt][h*2+1] + b1) * cv.y;
                *(float2*)&out[(size_t)(rowg0 + rloc)*64 + d] = ov;
            }
        }
    }
}

// ================= launch =====================================================
extern "C" void kernel_launch(void* const* d_in, const int* in_sizes, int n_in,
                              void* d_out, int out_size) {
    const float* x      = (const float*)d_in[0];
    const float* Wh     = (const float*)d_in[1];
    const float* bh     = (const float*)d_in[2];
    const float* Wog    = (const float*)d_in[3];
    const float* bog    = (const float*)d_in[4];
    const float* gamma  = (const float*)d_in[5];
    const float* beta   = (const float*)d_in[6];
    const float* initcx = (const float*)d_in[7];
    float* out = (float*)d_out;

    static bool attr_done = false;
    if (!attr_done) {
        cudaFuncSetAttribute(k_mega, cudaFuncAttributeMaxDynamicSharedMemorySize, MEGA_SMEM_BYTES);
        attr_done = true;
    }

    kprep_w<<<48, 256>>>(Wh, Wog);
    k_mega<<<GRID_K34 + GRID_K7, 512, MEGA_SMEM_BYTES>>>(
        x, gamma, beta, bh, initcx, bog, out);
}